// round 11
// baseline (speedup 1.0000x reference)
#include <cuda_runtime.h>
#include <cuda_fp16.h>
#include <cstdint>
#include <math.h>

// ---------------------------------------------------------------------------
// VGG16-block3 features on outputs+styles [4,3,256,256], then
// loss = mean_{b,n} (1 - max_m xn[b,n].sn[b,m]),  C=768, N=M=4096.
//
// Full fp16 datapath (fp32 accumulate) on m16n8k16 MMA, cp.async-pipelined.
// Stacks run sequentially per input (batch 4 each) — batching both inputs
// (NIMG=8) regressed 47% by blowing the L2/TLB working set (round-9 lesson).
// Activations: zero-padded channel-pair half2 layout [C/2][H+2][W+4]; DATA
// AT COLUMN 2 (cols 0-1 and tail zero) so output column pairs are 8B-aligned
// -> STG.64 epilogue stores. Storage pair P=(chunk c, p) holds logical
// channels (16c+p, 16c+8+p). Weights permuted to match. Padded borders rely
// on .bss zero-init, never written.
// ---------------------------------------------------------------------------

#define BATCH 4
#define FEATC 768
#define FEATN 4096

__device__ __half2 g_pad0[(size_t)BATCH * 8 * 258 * 260];
__device__ __half2 g_pad1[(size_t)BATCH * 32 * 258 * 260];
__device__ __half2 g_pad2[(size_t)BATCH * 32 * 258 * 260];
__device__ __half2 g_pad3[(size_t)BATCH * 32 * 130 * 132];
__device__ __half2 g_pad4[(size_t)BATCH * 64 * 130 * 132];
__device__ __half2 g_pad5[(size_t)BATCH * 64 * 130 * 132];
__device__ __half2 g_pad6[(size_t)BATCH * 64 * 66 * 68];
__device__ __half2 g_f1[(size_t)BATCH * 128 * 66 * 68];
__device__ __half2 g_f2[(size_t)BATCH * 128 * 66 * 68];
__device__ __half2 g_f3[(size_t)BATCH * 128 * 66 * 68];
__device__ __half  g_xT[(size_t)BATCH * FEATN * FEATC];
__device__ __half  g_sT[(size_t)BATCH * FEATN * FEATC];
__device__ __half2 g_wH[870912];
__device__ float   g_maxsim[BATCH * FEATN];

#define MMA_F16(c, a, bfr) \
    asm volatile("mma.sync.aligned.m16n8k16.row.col.f32.f16.f16.f32 " \
        "{%0,%1,%2,%3}, {%4,%5,%6,%7}, {%8,%9}, {%0,%1,%2,%3};" \
        : "+f"((c)[0]), "+f"((c)[1]), "+f"((c)[2]), "+f"((c)[3]) \
        : "r"((a)[0]), "r"((a)[1]), "r"((a)[2]), "r"((a)[3]), \
          "r"((bfr)[0]), "r"((bfr)[1]))

__device__ __forceinline__ void cpa16(uint32_t dst, const void* src) {
    asm volatile("cp.async.cg.shared.global [%0], [%1], 16;" :: "r"(dst), "l"(src));
}
#define CPA_COMMIT() asm volatile("cp.async.commit_group;" ::: "memory")
#define CPA_WAIT1()  asm volatile("cp.async.wait_group 1;" ::: "memory")
#define CPA_WAIT0()  asm volatile("cp.async.wait_group 0;" ::: "memory")

// ---------------------------------------------------------------------------
// input normalization -> padded half2 pair layout (data at col 2)
// ---------------------------------------------------------------------------
__global__ void norm_input_pad_kernel(const float* __restrict__ in, __half2* __restrict__ out) {
    int i = blockIdx.x * blockDim.x + threadIdx.x;
    if (i >= BATCH * 3 * 65536) return;
    int x = i & 255, y = (i >> 8) & 255;
    int c = (i >> 16) % 3, b = i / (3 * 65536);
    const float mean[3] = {0.485f, 0.456f, 0.406f};
    const float stdv[3] = {0.229f, 0.224f, 0.225f};
    float v = (in[i] - mean[c]) / stdv[c];
    out[((size_t)(b * 8 + c) * 258 + 1 + y) * 260 + 2 + x] = __floats2half2_rn(v, 0.f);
}

// ---------------------------------------------------------------------------
// fused weight transform for all 7 layers:
// w[oc][ic][3x3] -> wH[seg + (c*OC+oc)*72 + t*8 + p]
// ---------------------------------------------------------------------------
__global__ void wtrans_all_kernel(const float* __restrict__ w0, const float* __restrict__ w1,
                                  const float* __restrict__ w2, const float* __restrict__ w3,
                                  const float* __restrict__ w4, const float* __restrict__ w5,
                                  const float* __restrict__ w6, __half2* __restrict__ wH) {
    const int i = blockIdx.x * blockDim.x + threadIdx.x;
    if (i >= 870912) return;
    const int ends[7] = {4608, 23040, 59904, 133632, 281088, 576000, 870912};
    const int OCt[7] = {64, 64, 128, 128, 256, 256, 256};
    const int Cint[7] = {3, 64, 64, 128, 128, 256, 256};
    int L = 0;
    while (i >= ends[L]) L++;
    int base = (L == 0) ? 0 : ends[L - 1];
    const float* wsrc[7] = {w0, w1, w2, w3, w4, w5, w6};
    const float* w = wsrc[L];
    int OC = OCt[L], Cin = Cint[L];
    int j = i - base;
    int within = j % 72;
    int t = within >> 3, p = within & 7;
    int oc = (j / 72) % OC;
    int c = j / (72 * OC);
    int ic0 = 16 * c + p, ic1 = ic0 + 8;
    float v0 = (ic0 < Cin) ? w[((size_t)oc * Cin + ic0) * 9 + t] : 0.f;
    float v1 = (ic1 < Cin) ? w[((size_t)oc * Cin + ic1) * 9 + t] : 0.f;
    wH[i] = __floats2half2_rn(v0, v1);
}

// ---------------------------------------------------------------------------
// fp16 implicit-GEMM 3x3 conv + bias + ReLU, cp.async double-buffered.
// Block 256 thr: 64 oc x 256 px (ROWS x COLS). Warps 2(oc) x 4(px).
// Data at padded col 2 -> epilogue pairs are 8B-aligned (STG.64).
// ---------------------------------------------------------------------------
template <int ROWS, int COLS>
__global__ __launch_bounds__(256, 2)
void conv_mma_f16(const __half2* __restrict__ in, const __half2* __restrict__ wH,
                  const float* __restrict__ bias, __half2* __restrict__ out,
                  int chunks, int OC) {
    constexpr int PW2 = COLS + 4;
    constexpr int PR = ROWS + 2;
    constexpr int ICS2 = (PR * PW2 + 31) / 32 * 32 + 8;
    constexpr int WS_SIZE = 64 * 84;
    constexpr int PATCH_SIZE = 8 * ICS2;
    constexpr int BUF = WS_SIZE + PATCH_SIZE;
    extern __shared__ __half2 sm[];

    const int tid = threadIdx.x;
    const int wid = tid >> 5, lane = tid & 31;
    const int wm = wid & 1, wn = wid >> 1;
    const int grp = lane >> 2, tg = lane & 3;

    const int b = blockIdx.z;
    const int ocg = blockIdx.y;
    const int y0 = blockIdx.x * ROWS;
    const size_t plane2 = (size_t)(COLS + 2) * PW2;

    const __half2* inB = in + (size_t)b * (chunks * 8) * plane2;
    const uint32_t sm_u32 = (uint32_t)__cvta_generic_to_shared(sm);

    int nb[8];
#pragma unroll
    for (int nf = 0; nf < 8; nf++) {
        int n = wn * 64 + nf * 8 + grp;
        nb[nf] = (n / COLS) * PW2 + (n % COLS) + 1;   // data col 2, halo starts col 1
    }

    float acc[2][8][4];
#pragma unroll
    for (int mf = 0; mf < 2; mf++)
#pragma unroll
        for (int nf = 0; nf < 8; nf++)
#pragma unroll
            for (int k = 0; k < 4; k++) acc[mf][nf][k] = 0.f;

    auto prefetch = [&](int c, int bi) {
        const __half2* wsrc = wH + ((size_t)c * OC + ocg * 64) * 72;
        uint32_t wdst = sm_u32 + (uint32_t)(bi * BUF) * 4;
        for (int id = tid; id < 1152; id += 256) {
            int oc = id / 18, q = id - oc * 18;
            cpa16(wdst + (oc * 84 + q * 4) * 4, wsrc + oc * 72 + q * 4);
        }
        uint32_t pdst = sm_u32 + (uint32_t)(bi * BUF + WS_SIZE) * 4;
        for (int rs = wid; rs < 8 * PR; rs += 8) {
            int pair = rs / PR, row = rs - pair * PR;
            const __half2* src = inB + (size_t)(c * 8 + pair) * plane2 + (size_t)(y0 + row) * PW2;
            uint32_t dst = pdst + (pair * ICS2 + row * PW2) * 4;
            for (int x = lane; x < PW2 / 4; x += 32)
                cpa16(dst + x * 16, src + x * 4);
        }
    };

    prefetch(0, 0);
    CPA_COMMIT();

    for (int c = 0; c < chunks; c++) {
        const int bi = c & 1;
        if (c > 0) __syncthreads();
        if (c + 1 < chunks) {
            prefetch(c + 1, bi ^ 1);
            CPA_COMMIT();
            CPA_WAIT1();
        } else {
            CPA_WAIT0();
        }
        __syncthreads();

        const uint32_t* Wsu = (const uint32_t*)(sm + bi * BUF);
        const uint32_t* patchu = (const uint32_t*)(sm + bi * BUF + WS_SIZE);

#pragma unroll
        for (int tap = 0; tap < 9; tap++) {
            const int toff = (tap / 3) * PW2 + (tap % 3);
            uint32_t a[2][4];
#pragma unroll
            for (int mf = 0; mf < 2; mf++) {
                int m = wm * 32 + mf * 16 + grp;
                a[mf][0] = Wsu[m * 84 + tap * 8 + tg];
                a[mf][1] = Wsu[(m + 8) * 84 + tap * 8 + tg];
                a[mf][2] = Wsu[m * 84 + tap * 8 + tg + 4];
                a[mf][3] = Wsu[(m + 8) * 84 + tap * 8 + tg + 4];
            }
#pragma unroll
            for (int nf = 0; nf < 8; nf++) {
                uint32_t bf[2];
                bf[0] = patchu[tg * ICS2 + nb[nf] + toff];
                bf[1] = patchu[(tg + 4) * ICS2 + nb[nf] + toff];
                MMA_F16(acc[0][nf], a[0], bf);
                MMA_F16(acc[1][nf], a[1], bf);
            }
        }
    }

    __half2* outB = out + (size_t)b * (OC / 2) * plane2;
#pragma unroll
    for (int mf = 0; mf < 2; mf++) {
        int oc = ocg * 64 + wm * 32 + mf * 16 + grp;
        float bv0 = bias[oc], bv1 = bias[oc + 8];
        int P = (ocg * 4 + wm * 2 + mf) * 8 + grp;
#pragma unroll
        for (int nf = 0; nf < 8; nf++) {
            int n = wn * 64 + nf * 8 + tg * 2;
            int rp = n / COLS, col = n % COLS;
            __half2* o = outB + (size_t)P * plane2 + (size_t)(y0 + 1 + rp) * PW2 + 2 + col;
            __half2 h0 = __floats2half2_rn(fmaxf(acc[mf][nf][0] + bv0, 0.f),
                                           fmaxf(acc[mf][nf][2] + bv1, 0.f));
            __half2 h1 = __floats2half2_rn(fmaxf(acc[mf][nf][1] + bv0, 0.f),
                                           fmaxf(acc[mf][nf][3] + bv1, 0.f));
            float2 st;
            st.x = __uint_as_float(*(uint32_t*)&h0);
            st.y = __uint_as_float(*(uint32_t*)&h1);
            *(float2*)o = st;   // 8B-aligned: col even, data at col 2
        }
    }
}

// ---------------------------------------------------------------------------
// 2x2 maxpool on padded half2 buffers (data at col 2)
// ---------------------------------------------------------------------------
__global__ void maxpool_pad_kernel(const __half2* __restrict__ in, __half2* __restrict__ out,
                                   int pairs, int H, int W) {
    int Ho = H / 2, Wo = W / 2;
    long total = (long)BATCH * pairs * Ho * Wo;
    long i = (long)blockIdx.x * blockDim.x + threadIdx.x;
    if (i >= total) return;
    int x = (int)(i % Wo);
    long t = i / Wo;
    int y = (int)(t % Ho); t /= Ho;
    int p = (int)(t % pairs);
    int b = (int)(t / pairs);
    const __half2* s = in + ((size_t)(b * pairs + p) * (H + 2) + (1 + 2 * y)) * (W + 4) + 2 + 2 * x;
    __half2 m = __hmax2(__hmax2(s[0], s[1]), __hmax2(s[W + 4], s[W + 5]));
    out[((size_t)(b * pairs + p) * (Ho + 2) + 1 + y) * (Wo + 4) + 2 + x] = m;
}

// ---------------------------------------------------------------------------
// padded f1|f2|f3 [128P][66][68] half2 -> [B][N][384] half2 rows (data col 2)
// ---------------------------------------------------------------------------
__global__ void feat_transpose_kernel(const __half2* __restrict__ f1, const __half2* __restrict__ f2,
                                      const __half2* __restrict__ f3, __half2* __restrict__ out) {
    __shared__ __half2 s[32][33];
    int b = blockIdx.z;
    int Pg = blockIdx.y * 32;
    int n0 = blockIdx.x * 32;
    const __half2* fb = (Pg < 128) ? f1 : (Pg < 256 ? f2 : f3);
    int Pl = Pg & 127;
    int tx = threadIdx.x, ty = threadIdx.y;
    int n = n0 + tx, yy = n >> 6, xx = n & 63;
    size_t base = (size_t)b * 128 * 4488;
#pragma unroll
    for (int i = 0; i < 4; i++)
        s[ty + 8 * i][tx] = fb[base + (size_t)(Pl + ty + 8 * i) * 4488 + (1 + yy) * 68 + 2 + xx];
    __syncthreads();
#pragma unroll
    for (int i = 0; i < 4; i++)
        out[((size_t)b * FEATN + n0 + ty + 8 * i) * 384 + Pg + tx] = s[tx][ty + 8 * i];
}

// ---------------------------------------------------------------------------
// row L2-normalize half rows [B*N][768] in place; warp per row, fp32 math
// ---------------------------------------------------------------------------
__global__ __launch_bounds__(256)
void rownorm_rows_kernel(__half2* __restrict__ f) {
    int row = blockIdx.x * 8 + (threadIdx.x >> 5);
    int lane = threadIdx.x & 31;
    __half2* p = f + (size_t)row * 384;
    float2 v[12];
    float ssq = 0.f;
#pragma unroll
    for (int k = 0; k < 12; k++) {
        v[k] = __half22float2(p[k * 32 + lane]);
        ssq = fmaf(v[k].x, v[k].x, fmaf(v[k].y, v[k].y, ssq));
    }
#pragma unroll
    for (int st = 16; st > 0; st >>= 1)
        ssq += __shfl_xor_sync(0xffffffff, ssq, st);
    float inv = 1.0f / (sqrtf(ssq) + 1e-8f);
#pragma unroll
    for (int k = 0; k < 12; k++)
        p[k * 32 + lane] = __floats2half2_rn(v[k].x * inv, v[k].y * inv);
}

__global__ void initmax_kernel(float* __restrict__ g) {
    int i = blockIdx.x * blockDim.x + threadIdx.x;
    if (i < BATCH * FEATN) g[i] = 0.f;
}

// ---------------------------------------------------------------------------
// fp16 mma sim + row-max, cp.async double-buffered.
// Block 128x128, warps 2x4 (64x32), K-chunk 64 (32 half2), 12 chunks.
// ---------------------------------------------------------------------------
#define SIM_TILE 4608

__global__ __launch_bounds__(256, 2)
void simmax_mma_f16(const __half* __restrict__ xT, const __half* __restrict__ sT,
                    float* __restrict__ gmax) {
    extern __shared__ __half2 sm[];

    const int b = blockIdx.z;
    const int nbase = blockIdx.y * 128;
    const int mbase = blockIdx.x * 128;
    const int tid = threadIdx.x;
    const int wid = tid >> 5, lane = tid & 31;
    const int wm = wid & 1, wn = wid >> 1;
    const int grp = lane >> 2, tg = lane & 3;

    const __half2* xb2 = (const __half2*)xT + ((size_t)b * FEATN + nbase) * 384;
    const __half2* sp2 = (const __half2*)sT + ((size_t)b * FEATN + mbase) * 384;
    const uint32_t sm_u32 = (uint32_t)__cvta_generic_to_shared(sm);

    float acc[4][4][4];
#pragma unroll
    for (int mf = 0; mf < 4; mf++)
#pragma unroll
        for (int nf = 0; nf < 4; nf++)
#pragma unroll
            for (int k = 0; k < 4; k++) acc[mf][nf][k] = 0.f;

    auto prefetch = [&](int chunk, int bi) {
        const int kc2 = chunk * 32;
        uint32_t abase = sm_u32 + (uint32_t)(bi * 2 * SIM_TILE) * 4;
        uint32_t bbase = abase + SIM_TILE * 4;
#pragma unroll
        for (int i = 0; i < 4; i++) {
            int id = tid + i * 256;
            int r = id >> 3, q = (id & 7) * 4;
            cpa16(abase + (r * 36 + q) * 4, xb2 + (size_t)r * 384 + kc2 + q);
            cpa16(bbase + (r * 36 + q) * 4, sp2 + (size_t)r * 384 + kc2 + q);
        }
    };

    prefetch(0, 0);
    CPA_COMMIT();

    for (int chunk = 0; chunk < 12; chunk++) {
        const int bi = chunk & 1;
        if (chunk > 0) __syncthreads();
        if (chunk + 1 < 12) {
            prefetch(chunk + 1, bi ^ 1);
            CPA_COMMIT();
            CPA_WAIT1();
        } else {
            CPA_WAIT0();
        }
        __syncthreads();

        const uint32_t* Au = (const uint32_t*)(sm + bi * 2 * SIM_TILE);
        const uint32_t* Bu = Au + SIM_TILE;

#pragma unroll
        for (int ks = 0; ks < 4; ks++) {
            const int kk = ks * 8;
            uint32_t a[4][4];
#pragma unroll
            for (int mf = 0; mf < 4; mf++) {
                int m = wm * 64 + mf * 16 + grp;
                a[mf][0] = Au[m * 36 + kk + tg];
                a[mf][1] = Au[(m + 8) * 36 + kk + tg];
                a[mf][2] = Au[m * 36 + kk + tg + 4];
                a[mf][3] = Au[(m + 8) * 36 + kk + tg + 4];
            }
#pragma unroll
            for (int nf = 0; nf < 4; nf++) {
                int n = wn * 32 + nf * 8 + grp;
                uint32_t bf[2];
                bf[0] = Bu[n * 36 + kk + tg];
                bf[1] = Bu[n * 36 + kk + tg + 4];
                MMA_F16(acc[0][nf], a[0], bf);
                MMA_F16(acc[1][nf], a[1], bf);
                MMA_F16(acc[2][nf], a[2], bf);
                MMA_F16(acc[3][nf], a[3], bf);
            }
        }
    }

#pragma unroll
    for (int mf = 0; mf < 4; mf++) {
        float r0 = 0.f, r1 = 0.f;
#pragma unroll
        for (int nf = 0; nf < 4; nf++) {
            r0 = fmaxf(r0, fmaxf(acc[mf][nf][0], acc[mf][nf][1]));
            r1 = fmaxf(r1, fmaxf(acc[mf][nf][2], acc[mf][nf][3]));
        }
        r0 = fmaxf(r0, __shfl_xor_sync(0xffffffff, r0, 1));
        r0 = fmaxf(r0, __shfl_xor_sync(0xffffffff, r0, 2));
        r1 = fmaxf(r1, __shfl_xor_sync(0xffffffff, r1, 1));
        r1 = fmaxf(r1, __shfl_xor_sync(0xffffffff, r1, 2));
        if (tg == 0) {
            int row = nbase + wm * 64 + mf * 16 + grp;
            atomicMax((int*)&gmax[(size_t)b * FEATN + row], __float_as_int(r0));
            atomicMax((int*)&gmax[(size_t)b * FEATN + row + 8], __float_as_int(r1));
        }
    }
}

// ---------------------------------------------------------------------------
// final reduction
// ---------------------------------------------------------------------------
__global__ void final_loss_kernel(const float* __restrict__ gmax, float* __restrict__ out) {
    __shared__ double sm[256];
    double s = 0.0;
    for (int i = threadIdx.x; i < BATCH * FEATN; i += 256)
        s += 1.0 - (double)gmax[i];
    sm[threadIdx.x] = s;
    __syncthreads();
    for (int st = 128; st > 0; st >>= 1) {
        if (threadIdx.x < st) sm[threadIdx.x] += sm[threadIdx.x + st];
        __syncthreads();
    }
    if (threadIdx.x == 0)
        out[0] = (float)(sm[0] / (double)(BATCH * FEATN));
}

// ---------------------------------------------------------------------------
// host orchestration
// ---------------------------------------------------------------------------
static constexpr int conv_smem(int R, int C) {
    int PW2 = C + 4, PR = R + 2;
    int ICS2 = (PR * PW2 + 31) / 32 * 32 + 8;
    return 2 * (64 * 84 + 8 * ICS2) * 4;
}
#define CS_R1 conv_smem(1, 256)
#define CS_R2 conv_smem(2, 128)
#define CS_R4 conv_smem(4, 64)
#define SIM_SMEM (4 * SIM_TILE * 4)

static void run_stack(const float* img, __half2* wH, const float* const* bs,
                      __half2* pad0, __half2* pad1, __half2* pad2, __half2* pad3,
                      __half2* pad4, __half2* pad5, __half2* pad6,
                      __half2* f1, __half2* f2, __half2* f3, __half* featT) {
    const long o0 = 0, o1 = 4608, o2 = 23040, o3 = 59904,
               o4 = 133632, o5 = 281088, o6 = 576000;

    norm_input_pad_kernel<<<(BATCH * 3 * 65536 + 255) / 256, 256>>>(img, pad0);

    conv_mma_f16<1, 256><<<dim3(256, 1, BATCH), 256, CS_R1>>>(pad0, wH + o0, bs[0], pad1, 1, 64);
    conv_mma_f16<1, 256><<<dim3(256, 1, BATCH), 256, CS_R1>>>(pad1, wH + o1, bs[1], pad2, 4, 64);
    {
        long total = (long)BATCH * 32 * 128 * 128;
        maxpool_pad_kernel<<<(unsigned)((total + 255) / 256), 256>>>(pad2, pad3, 32, 256, 256);
    }
    conv_mma_f16<2, 128><<<dim3(64, 2, BATCH), 256, CS_R2>>>(pad3, wH + o2, bs[2], pad4, 4, 128);
    conv_mma_f16<2, 128><<<dim3(64, 2, BATCH), 256, CS_R2>>>(pad4, wH + o3, bs[3], pad5, 8, 128);
    {
        long total = (long)BATCH * 64 * 64 * 64;
        maxpool_pad_kernel<<<(unsigned)((total + 255) / 256), 256>>>(pad5, pad6, 64, 128, 128);
    }
    conv_mma_f16<4, 64><<<dim3(16, 4, BATCH), 256, CS_R4>>>(pad6, wH + o4, bs[4], f1, 8, 256);
    conv_mma_f16<4, 64><<<dim3(16, 4, BATCH), 256, CS_R4>>>(f1, wH + o5, bs[5], f2, 16, 256);
    conv_mma_f16<4, 64><<<dim3(16, 4, BATCH), 256, CS_R4>>>(f2, wH + o6, bs[6], f3, 16, 256);

    feat_transpose_kernel<<<dim3(128, 12, BATCH), dim3(32, 8)>>>(f1, f2, f3, (__half2*)featT);
    rownorm_rows_kernel<<<BATCH * FEATN / 8, 256>>>((__half2*)featT);
}

extern "C" void kernel_launch(void* const* d_in, const int* in_sizes, int n_in,
                              void* d_out, int out_size) {
    (void)in_sizes; (void)n_in; (void)out_size;

    __half2 *pad0, *pad1, *pad2, *pad3, *pad4, *pad5, *pad6, *f1, *f2, *f3, *wH;
    __half *xT, *sT;
    float *gmax;
    cudaGetSymbolAddress((void**)&pad0, g_pad0);
    cudaGetSymbolAddress((void**)&pad1, g_pad1);
    cudaGetSymbolAddress((void**)&pad2, g_pad2);
    cudaGetSymbolAddress((void**)&pad3, g_pad3);
    cudaGetSymbolAddress((void**)&pad4, g_pad4);
    cudaGetSymbolAddress((void**)&pad5, g_pad5);
    cudaGetSymbolAddress((void**)&pad6, g_pad6);
    cudaGetSymbolAddress((void**)&f1, g_f1);
    cudaGetSymbolAddress((void**)&f2, g_f2);
    cudaGetSymbolAddress((void**)&f3, g_f3);
    cudaGetSymbolAddress((void**)&xT, g_xT);
    cudaGetSymbolAddress((void**)&sT, g_sT);
    cudaGetSymbolAddress((void**)&wH, g_wH);
    cudaGetSymbolAddress((void**)&gmax, g_maxsim);

    cudaFuncSetAttribute(conv_mma_f16<1, 256>, cudaFuncAttributeMaxDynamicSharedMemorySize, CS_R1);
    cudaFuncSetAttribute(conv_mma_f16<2, 128>, cudaFuncAttributeMaxDynamicSharedMemorySize, CS_R2);
    cudaFuncSetAttribute(conv_mma_f16<4, 64>,  cudaFuncAttributeMaxDynamicSharedMemorySize, CS_R4);
    cudaFuncSetAttribute(simmax_mma_f16, cudaFuncAttributeMaxDynamicSharedMemorySize, SIM_SMEM);

    const float* outputs = (const float*)d_in[0];
    const float* styles  = (const float*)d_in[1];
    const float* bs[7];
    for (int i = 0; i < 7; i++) bs[i] = (const float*)d_in[3 + 2 * i];

    // fused weight transform (single launch)
    wtrans_all_kernel<<<(870912 + 255) / 256, 256>>>(
        (const float*)d_in[2], (const float*)d_in[4], (const float*)d_in[6],
        (const float*)d_in[8], (const float*)d_in[10], (const float*)d_in[12],
        (const float*)d_in[14], wH);

    initmax_kernel<<<(BATCH * FEATN + 255) / 256, 256>>>(gmax);

    run_stack(outputs, wH, bs, pad0, pad1, pad2, pad3, pad4, pad5, pad6, f1, f2, f3, xT);
    run_stack(styles,  wH, bs, pad0, pad1, pad2, pad3, pad4, pad5, pad6, f1, f2, f3, sT);

    simmax_mma_f16<<<dim3(FEATN / 128, FEATN / 128, BATCH), 256, SIM_SMEM>>>(xT, sT, gmax);
    final_loss_kernel<<<1, 256>>>(gmax, (float*)d_out);
}

// round 13
// speedup vs baseline: 1.4837x; 1.4837x over previous
#include <cuda_runtime.h>
#include <cuda_fp16.h>
#include <cstdint>
#include <math.h>

// ---------------------------------------------------------------------------
// VGG16-block3 features on outputs+styles [4,3,256,256], then
// loss = mean_{b,n} (1 - max_m xn[b,n].sn[b,m]),  C=768, N=M=4096.
//
// Full fp16 datapath (fp32 accumulate) on m16n8k16 MMA, cp.async-pipelined.
// Activations: zero-padded channel-pair half2 layout [C/2][H+2][W+4]; storage
// pair P=(chunk c, p) holds logical channels (16c+p, 16c+8+p). Weights
// permuted to match. Padded borders rely on .bss zero-init, never written.
// CONTROL RUN: byte-exact round-8 configuration (measured 1110.3 us).
// ---------------------------------------------------------------------------

#define BATCH 4
#define FEATC 768
#define FEATN 4096

__device__ __half2 g_pad0[(size_t)BATCH * 8 * 258 * 260];
__device__ __half2 g_pad1[(size_t)BATCH * 32 * 258 * 260];
__device__ __half2 g_pad2[(size_t)BATCH * 32 * 258 * 260];
__device__ __half2 g_pad3[(size_t)BATCH * 32 * 130 * 132];
__device__ __half2 g_pad4[(size_t)BATCH * 64 * 130 * 132];
__device__ __half2 g_pad5[(size_t)BATCH * 64 * 130 * 132];
__device__ __half2 g_pad6[(size_t)BATCH * 64 * 66 * 68];
__device__ __half2 g_f1[(size_t)BATCH * 128 * 66 * 68];
__device__ __half2 g_f2[(size_t)BATCH * 128 * 66 * 68];
__device__ __half2 g_f3[(size_t)BATCH * 128 * 66 * 68];
__device__ __half  g_xT[(size_t)BATCH * FEATN * FEATC];
__device__ __half  g_sT[(size_t)BATCH * FEATN * FEATC];
__device__ __half2 g_wH[870912];
__device__ float   g_maxsim[BATCH * FEATN];

#define MMA_F16(c, a, bfr) \
    asm volatile("mma.sync.aligned.m16n8k16.row.col.f32.f16.f16.f32 " \
        "{%0,%1,%2,%3}, {%4,%5,%6,%7}, {%8,%9}, {%0,%1,%2,%3};" \
        : "+f"((c)[0]), "+f"((c)[1]), "+f"((c)[2]), "+f"((c)[3]) \
        : "r"((a)[0]), "r"((a)[1]), "r"((a)[2]), "r"((a)[3]), \
          "r"((bfr)[0]), "r"((bfr)[1]))

__device__ __forceinline__ void cpa16(uint32_t dst, const void* src) {
    asm volatile("cp.async.cg.shared.global [%0], [%1], 16;" :: "r"(dst), "l"(src));
}
#define CPA_COMMIT() asm volatile("cp.async.commit_group;" ::: "memory")
#define CPA_WAIT1()  asm volatile("cp.async.wait_group 1;" ::: "memory")
#define CPA_WAIT0()  asm volatile("cp.async.wait_group 0;" ::: "memory")

// ---------------------------------------------------------------------------
// input normalization -> padded half2 pair layout (pairs (p, p+8); ch>=3 zero)
// ---------------------------------------------------------------------------
__global__ void norm_input_pad_kernel(const float* __restrict__ in, __half2* __restrict__ out) {
    int i = blockIdx.x * blockDim.x + threadIdx.x;
    if (i >= BATCH * 3 * 65536) return;
    int x = i & 255, y = (i >> 8) & 255;
    int c = (i >> 16) % 3, b = i / (3 * 65536);
    const float mean[3] = {0.485f, 0.456f, 0.406f};
    const float stdv[3] = {0.229f, 0.224f, 0.225f};
    float v = (in[i] - mean[c]) / stdv[c];
    out[((size_t)(b * 8 + c) * 258 + 1 + y) * 260 + 1 + x] = __floats2half2_rn(v, 0.f);
}

// ---------------------------------------------------------------------------
// weight transform: w[oc][ic][3x3] -> wH[(c*OC+oc)*72 + t*8 + p]
// ---------------------------------------------------------------------------
__global__ void wtrans_kernel(const float* __restrict__ w, __half2* __restrict__ wH,
                              int OC, int Cin, int total) {
    int i = blockIdx.x * blockDim.x + threadIdx.x;
    if (i >= total) return;
    int within = i % 72;
    int t = within >> 3, p = within & 7;
    int oc = (i / 72) % OC;
    int c = i / (72 * OC);
    int ic0 = 16 * c + p, ic1 = ic0 + 8;
    float v0 = (ic0 < Cin) ? w[((size_t)oc * Cin + ic0) * 9 + t] : 0.f;
    float v1 = (ic1 < Cin) ? w[((size_t)oc * Cin + ic1) * 9 + t] : 0.f;
    wH[i] = __floats2half2_rn(v0, v1);
}

// ---------------------------------------------------------------------------
// fp16 implicit-GEMM 3x3 conv + bias + ReLU, cp.async double-buffered.
// Block 256 thr: 64 oc x 256 px (ROWS x COLS). Warps 2(oc) x 4(px).
// ---------------------------------------------------------------------------
template <int ROWS, int COLS>
__global__ __launch_bounds__(256, 2)
void conv_mma_f16(const __half2* __restrict__ in, const __half2* __restrict__ wH,
                  const float* __restrict__ bias, __half2* __restrict__ out,
                  int chunks, int OC) {
    constexpr int PW2 = COLS + 4;
    constexpr int PR = ROWS + 2;
    constexpr int ICS2 = (PR * PW2 + 31) / 32 * 32 + 8;
    constexpr int WS_SIZE = 64 * 84;
    constexpr int PATCH_SIZE = 8 * ICS2;
    constexpr int BUF = WS_SIZE + PATCH_SIZE;
    extern __shared__ __half2 sm[];

    const int tid = threadIdx.x;
    const int wid = tid >> 5, lane = tid & 31;
    const int wm = wid & 1, wn = wid >> 1;
    const int grp = lane >> 2, tg = lane & 3;

    const int b = blockIdx.z;
    const int ocg = blockIdx.y;
    const int y0 = blockIdx.x * ROWS;
    const size_t plane2 = (size_t)(COLS + 2) * PW2;

    const __half2* inB = in + (size_t)b * (chunks * 8) * plane2;
    const uint32_t sm_u32 = (uint32_t)__cvta_generic_to_shared(sm);

    int nb[8];
#pragma unroll
    for (int nf = 0; nf < 8; nf++) {
        int n = wn * 64 + nf * 8 + grp;
        nb[nf] = (n / COLS) * PW2 + (n % COLS);
    }

    float acc[2][8][4];
#pragma unroll
    for (int mf = 0; mf < 2; mf++)
#pragma unroll
        for (int nf = 0; nf < 8; nf++)
#pragma unroll
            for (int k = 0; k < 4; k++) acc[mf][nf][k] = 0.f;

    auto prefetch = [&](int c, int bi) {
        const __half2* wsrc = wH + ((size_t)c * OC + ocg * 64) * 72;
        uint32_t wdst = sm_u32 + (uint32_t)(bi * BUF) * 4;
        for (int id = tid; id < 1152; id += 256) {
            int oc = id / 18, q = id - oc * 18;
            cpa16(wdst + (oc * 84 + q * 4) * 4, wsrc + oc * 72 + q * 4);
        }
        uint32_t pdst = sm_u32 + (uint32_t)(bi * BUF + WS_SIZE) * 4;
        for (int rs = wid; rs < 8 * PR; rs += 8) {
            int pair = rs / PR, row = rs - pair * PR;
            const __half2* src = inB + (size_t)(c * 8 + pair) * plane2 + (size_t)(y0 + row) * PW2;
            uint32_t dst = pdst + (pair * ICS2 + row * PW2) * 4;
            for (int x = lane; x < PW2 / 4; x += 32)
                cpa16(dst + x * 16, src + x * 4);
        }
    };

    prefetch(0, 0);
    CPA_COMMIT();

    for (int c = 0; c < chunks; c++) {
        const int bi = c & 1;
        if (c > 0) __syncthreads();
        if (c + 1 < chunks) {
            prefetch(c + 1, bi ^ 1);
            CPA_COMMIT();
            CPA_WAIT1();
        } else {
            CPA_WAIT0();
        }
        __syncthreads();

        const uint32_t* Wsu = (const uint32_t*)(sm + bi * BUF);
        const uint32_t* patchu = (const uint32_t*)(sm + bi * BUF + WS_SIZE);

#pragma unroll
        for (int tap = 0; tap < 9; tap++) {
            const int toff = (tap / 3) * PW2 + (tap % 3);
            uint32_t a[2][4];
#pragma unroll
            for (int mf = 0; mf < 2; mf++) {
                int m = wm * 32 + mf * 16 + grp;
                a[mf][0] = Wsu[m * 84 + tap * 8 + tg];
                a[mf][1] = Wsu[(m + 8) * 84 + tap * 8 + tg];
                a[mf][2] = Wsu[m * 84 + tap * 8 + tg + 4];
                a[mf][3] = Wsu[(m + 8) * 84 + tap * 8 + tg + 4];
            }
#pragma unroll
            for (int nf = 0; nf < 8; nf++) {
                uint32_t bf[2];
                bf[0] = patchu[tg * ICS2 + nb[nf] + toff];
                bf[1] = patchu[(tg + 4) * ICS2 + nb[nf] + toff];
                MMA_F16(acc[0][nf], a[0], bf);
                MMA_F16(acc[1][nf], a[1], bf);
            }
        }
    }

    __half2* outB = out + (size_t)b * (OC / 2) * plane2;
#pragma unroll
    for (int mf = 0; mf < 2; mf++) {
        int oc = ocg * 64 + wm * 32 + mf * 16 + grp;
        float bv0 = bias[oc], bv1 = bias[oc + 8];
        int P = (ocg * 4 + wm * 2 + mf) * 8 + grp;
#pragma unroll
        for (int nf = 0; nf < 8; nf++) {
            int n = wn * 64 + nf * 8 + tg * 2;
            int rp = n / COLS, col = n % COLS;
            __half2* o = outB + (size_t)P * plane2 + (size_t)(y0 + 1 + rp) * PW2 + 1 + col;
            o[0] = __floats2half2_rn(fmaxf(acc[mf][nf][0] + bv0, 0.f),
                                     fmaxf(acc[mf][nf][2] + bv1, 0.f));
            o[1] = __floats2half2_rn(fmaxf(acc[mf][nf][1] + bv0, 0.f),
                                     fmaxf(acc[mf][nf][3] + bv1, 0.f));
        }
    }
}

// ---------------------------------------------------------------------------
// 2x2 maxpool on padded half2 buffers
// ---------------------------------------------------------------------------
__global__ void maxpool_pad_kernel(const __half2* __restrict__ in, __half2* __restrict__ out,
                                   int pairs, int H, int W) {
    int Ho = H / 2, Wo = W / 2;
    long total = (long)BATCH * pairs * Ho * Wo;
    long i = (long)blockIdx.x * blockDim.x + threadIdx.x;
    if (i >= total) return;
    int x = (int)(i % Wo);
    long t = i / Wo;
    int y = (int)(t % Ho); t /= Ho;
    int p = (int)(t % pairs);
    int b = (int)(t / pairs);
    const __half2* s = in + ((size_t)(b * pairs + p) * (H + 2) + (1 + 2 * y)) * (W + 4) + 1 + 2 * x;
    __half2 m = __hmax2(__hmax2(s[0], s[1]), __hmax2(s[W + 4], s[W + 5]));
    out[((size_t)(b * pairs + p) * (Ho + 2) + 1 + y) * (Wo + 4) + 1 + x] = m;
}

// ---------------------------------------------------------------------------
// padded f1|f2|f3 [128P][66][68] half2 -> [B][N][384] half2 rows
// ---------------------------------------------------------------------------
__global__ void feat_transpose_kernel(const __half2* __restrict__ f1, const __half2* __restrict__ f2,
                                      const __half2* __restrict__ f3, __half2* __restrict__ out) {
    __shared__ __half2 s[32][33];
    int b = blockIdx.z;
    int Pg = blockIdx.y * 32;
    int n0 = blockIdx.x * 32;
    const __half2* fb = (Pg < 128) ? f1 : (Pg < 256 ? f2 : f3);
    int Pl = Pg & 127;
    int tx = threadIdx.x, ty = threadIdx.y;
    int n = n0 + tx, yy = n >> 6, xx = n & 63;
    size_t base = (size_t)b * 128 * 4488;
#pragma unroll
    for (int i = 0; i < 4; i++)
        s[ty + 8 * i][tx] = fb[base + (size_t)(Pl + ty + 8 * i) * 4488 + (1 + yy) * 68 + 1 + xx];
    __syncthreads();
#pragma unroll
    for (int i = 0; i < 4; i++)
        out[((size_t)b * FEATN + n0 + ty + 8 * i) * 384 + Pg + tx] = s[tx][ty + 8 * i];
}

// ---------------------------------------------------------------------------
// row L2-normalize half rows [B*N][768] in place; warp per row, fp32 math
// ---------------------------------------------------------------------------
__global__ __launch_bounds__(256)
void rownorm_rows_kernel(__half2* __restrict__ f) {
    int row = blockIdx.x * 8 + (threadIdx.x >> 5);
    int lane = threadIdx.x & 31;
    __half2* p = f + (size_t)row * 384;
    float2 v[12];
    float ssq = 0.f;
#pragma unroll
    for (int k = 0; k < 12; k++) {
        v[k] = __half22float2(p[k * 32 + lane]);
        ssq = fmaf(v[k].x, v[k].x, fmaf(v[k].y, v[k].y, ssq));
    }
#pragma unroll
    for (int st = 16; st > 0; st >>= 1)
        ssq += __shfl_xor_sync(0xffffffff, ssq, st);
    float inv = 1.0f / (sqrtf(ssq) + 1e-8f);
#pragma unroll
    for (int k = 0; k < 12; k++)
        p[k * 32 + lane] = __floats2half2_rn(v[k].x * inv, v[k].y * inv);
}

__global__ void initmax_kernel(float* __restrict__ g) {
    int i = blockIdx.x * blockDim.x + threadIdx.x;
    if (i < BATCH * FEATN) g[i] = 0.f;
}

// ---------------------------------------------------------------------------
// fp16 mma sim + row-max, cp.async double-buffered.
// Block 128x128, warps 2x4 (64x32), K-chunk 64 (32 half2), 12 chunks.
// ---------------------------------------------------------------------------
#define SIM_TILE 4608

__global__ __launch_bounds__(256, 2)
void simmax_mma_f16(const __half* __restrict__ xT, const __half* __restrict__ sT,
                    float* __restrict__ gmax) {
    extern __shared__ __half2 sm[];

    const int b = blockIdx.z;
    const int nbase = blockIdx.y * 128;
    const int mbase = blockIdx.x * 128;
    const int tid = threadIdx.x;
    const int wid = tid >> 5, lane = tid & 31;
    const int wm = wid & 1, wn = wid >> 1;
    const int grp = lane >> 2, tg = lane & 3;

    const __half2* xb2 = (const __half2*)xT + ((size_t)b * FEATN + nbase) * 384;
    const __half2* sp2 = (const __half2*)sT + ((size_t)b * FEATN + mbase) * 384;
    const uint32_t sm_u32 = (uint32_t)__cvta_generic_to_shared(sm);

    float acc[4][4][4];
#pragma unroll
    for (int mf = 0; mf < 4; mf++)
#pragma unroll
        for (int nf = 0; nf < 4; nf++)
#pragma unroll
            for (int k = 0; k < 4; k++) acc[mf][nf][k] = 0.f;

    auto prefetch = [&](int chunk, int bi) {
        const int kc2 = chunk * 32;
        uint32_t abase = sm_u32 + (uint32_t)(bi * 2 * SIM_TILE) * 4;
        uint32_t bbase = abase + SIM_TILE * 4;
#pragma unroll
        for (int i = 0; i < 4; i++) {
            int id = tid + i * 256;
            int r = id >> 3, q = (id & 7) * 4;
            cpa16(abase + (r * 36 + q) * 4, xb2 + (size_t)r * 384 + kc2 + q);
            cpa16(bbase + (r * 36 + q) * 4, sp2 + (size_t)r * 384 + kc2 + q);
        }
    };

    prefetch(0, 0);
    CPA_COMMIT();

    for (int chunk = 0; chunk < 12; chunk++) {
        const int bi = chunk & 1;
        if (chunk > 0) __syncthreads();
        if (chunk + 1 < 12) {
            prefetch(chunk + 1, bi ^ 1);
            CPA_COMMIT();
            CPA_WAIT1();
        } else {
            CPA_WAIT0();
        }
        __syncthreads();

        const uint32_t* Au = (const uint32_t*)(sm + bi * 2 * SIM_TILE);
        const uint32_t* Bu = Au + SIM_TILE;

#pragma unroll
        for (int ks = 0; ks < 4; ks++) {
            const int kk = ks * 8;
            uint32_t a[4][4];
#pragma unroll
            for (int mf = 0; mf < 4; mf++) {
                int m = wm * 64 + mf * 16 + grp;
                a[mf][0] = Au[m * 36 + kk + tg];
                a[mf][1] = Au[(m + 8) * 36 + kk + tg];
                a[mf][2] = Au[m * 36 + kk + tg + 4];
                a[mf][3] = Au[(m + 8) * 36 + kk + tg + 4];
            }
#pragma unroll
            for (int nf = 0; nf < 4; nf++) {
                int n = wn * 32 + nf * 8 + grp;
                uint32_t bf[2];
                bf[0] = Bu[n * 36 + kk + tg];
                bf[1] = Bu[n * 36 + kk + tg + 4];
                MMA_F16(acc[0][nf], a[0], bf);
                MMA_F16(acc[1][nf], a[1], bf);
                MMA_F16(acc[2][nf], a[2], bf);
                MMA_F16(acc[3][nf], a[3], bf);
            }
        }
    }

#pragma unroll
    for (int mf = 0; mf < 4; mf++) {
        float r0 = 0.f, r1 = 0.f;
#pragma unroll
        for (int nf = 0; nf < 4; nf++) {
            r0 = fmaxf(r0, fmaxf(acc[mf][nf][0], acc[mf][nf][1]));
            r1 = fmaxf(r1, fmaxf(acc[mf][nf][2], acc[mf][nf][3]));
        }
        r0 = fmaxf(r0, __shfl_xor_sync(0xffffffff, r0, 1));
        r0 = fmaxf(r0, __shfl_xor_sync(0xffffffff, r0, 2));
        r1 = fmaxf(r1, __shfl_xor_sync(0xffffffff, r1, 1));
        r1 = fmaxf(r1, __shfl_xor_sync(0xffffffff, r1, 2));
        if (tg == 0) {
            int row = nbase + wm * 64 + mf * 16 + grp;
            atomicMax((int*)&gmax[(size_t)b * FEATN + row], __float_as_int(r0));
            atomicMax((int*)&gmax[(size_t)b * FEATN + row + 8], __float_as_int(r1));
        }
    }
}

// ---------------------------------------------------------------------------
// final reduction
// ---------------------------------------------------------------------------
__global__ void final_loss_kernel(const float* __restrict__ gmax, float* __restrict__ out) {
    __shared__ double sm[256];
    double s = 0.0;
    for (int i = threadIdx.x; i < BATCH * FEATN; i += 256)
        s += 1.0 - (double)gmax[i];
    sm[threadIdx.x] = s;
    __syncthreads();
    for (int st = 128; st > 0; st >>= 1) {
        if (threadIdx.x < st) sm[threadIdx.x] += sm[threadIdx.x + st];
        __syncthreads();
    }
    if (threadIdx.x == 0)
        out[0] = (float)(sm[0] / (double)(BATCH * FEATN));
}

// ---------------------------------------------------------------------------
// host orchestration
// ---------------------------------------------------------------------------
static constexpr int conv_smem(int R, int C) {
    int PW2 = C + 4, PR = R + 2;
    int ICS2 = (PR * PW2 + 31) / 32 * 32 + 8;
    return 2 * (64 * 84 + 8 * ICS2) * 4;
}
#define CS_R1 conv_smem(1, 256)
#define CS_R2 conv_smem(2, 128)
#define CS_R4 conv_smem(4, 64)
#define SIM_SMEM (4 * SIM_TILE * 4)

static void run_stack(const float* img, __half2* wH, const float* const* bs,
                      __half2* pad0, __half2* pad1, __half2* pad2, __half2* pad3,
                      __half2* pad4, __half2* pad5, __half2* pad6,
                      __half2* f1, __half2* f2, __half2* f3, __half* featT) {
    const long o0 = 0, o1 = 4608, o2 = 23040, o3 = 59904,
               o4 = 133632, o5 = 281088, o6 = 576000;

    norm_input_pad_kernel<<<(BATCH * 3 * 65536 + 255) / 256, 256>>>(img, pad0);

    conv_mma_f16<1, 256><<<dim3(256, 1, BATCH), 256, CS_R1>>>(pad0, wH + o0, bs[0], pad1, 1, 64);
    conv_mma_f16<1, 256><<<dim3(256, 1, BATCH), 256, CS_R1>>>(pad1, wH + o1, bs[1], pad2, 4, 64);
    {
        long total = (long)BATCH * 32 * 128 * 128;
        maxpool_pad_kernel<<<(unsigned)((total + 255) / 256), 256>>>(pad2, pad3, 32, 256, 256);
    }
    conv_mma_f16<2, 128><<<dim3(64, 2, BATCH), 256, CS_R2>>>(pad3, wH + o2, bs[2], pad4, 4, 128);
    conv_mma_f16<2, 128><<<dim3(64, 2, BATCH), 256, CS_R2>>>(pad4, wH + o3, bs[3], pad5, 8, 128);
    {
        long total = (long)BATCH * 64 * 64 * 64;
        maxpool_pad_kernel<<<(unsigned)((total + 255) / 256), 256>>>(pad5, pad6, 64, 128, 128);
    }
    conv_mma_f16<4, 64><<<dim3(16, 4, BATCH), 256, CS_R4>>>(pad6, wH + o4, bs[4], f1, 8, 256);
    conv_mma_f16<4, 64><<<dim3(16, 4, BATCH), 256, CS_R4>>>(f1, wH + o5, bs[5], f2, 16, 256);
    conv_mma_f16<4, 64><<<dim3(16, 4, BATCH), 256, CS_R4>>>(f2, wH + o6, bs[6], f3, 16, 256);

    feat_transpose_kernel<<<dim3(128, 12, BATCH), dim3(32, 8)>>>(f1, f2, f3, (__half2*)featT);
    rownorm_rows_kernel<<<BATCH * FEATN / 8, 256>>>((__half2*)featT);
}

extern "C" void kernel_launch(void* const* d_in, const int* in_sizes, int n_in,
                              void* d_out, int out_size) {
    (void)in_sizes; (void)n_in; (void)out_size;

    __half2 *pad0, *pad1, *pad2, *pad3, *pad4, *pad5, *pad6, *f1, *f2, *f3, *wH;
    __half *xT, *sT;
    float *gmax;
    cudaGetSymbolAddress((void**)&pad0, g_pad0);
    cudaGetSymbolAddress((void**)&pad1, g_pad1);
    cudaGetSymbolAddress((void**)&pad2, g_pad2);
    cudaGetSymbolAddress((void**)&pad3, g_pad3);
    cudaGetSymbolAddress((void**)&pad4, g_pad4);
    cudaGetSymbolAddress((void**)&pad5, g_pad5);
    cudaGetSymbolAddress((void**)&pad6, g_pad6);
    cudaGetSymbolAddress((void**)&f1, g_f1);
    cudaGetSymbolAddress((void**)&f2, g_f2);
    cudaGetSymbolAddress((void**)&f3, g_f3);
    cudaGetSymbolAddress((void**)&xT, g_xT);
    cudaGetSymbolAddress((void**)&sT, g_sT);
    cudaGetSymbolAddress((void**)&wH, g_wH);
    cudaGetSymbolAddress((void**)&gmax, g_maxsim);

    cudaFuncSetAttribute(conv_mma_f16<1, 256>, cudaFuncAttributeMaxDynamicSharedMemorySize, CS_R1);
    cudaFuncSetAttribute(conv_mma_f16<2, 128>, cudaFuncAttributeMaxDynamicSharedMemorySize, CS_R2);
    cudaFuncSetAttribute(conv_mma_f16<4, 64>,  cudaFuncAttributeMaxDynamicSharedMemorySize, CS_R4);
    cudaFuncSetAttribute(simmax_mma_f16, cudaFuncAttributeMaxDynamicSharedMemorySize, SIM_SMEM);

    const float* outputs = (const float*)d_in[0];
    const float* styles  = (const float*)d_in[1];
    const float* bs[7];
    for (int i = 0; i < 7; i++) bs[i] = (const float*)d_in[3 + 2 * i];

    const int cfg[7][3] = {{64,3,1},{64,64,4},{128,64,4},{128,128,8},
                           {256,128,8},{256,256,16},{256,256,16}};
    const long woff[7] = {0, 4608, 23040, 59904, 133632, 281088, 576000};
    const float* w[7];
    for (int i = 0; i < 7; i++) w[i] = (const float*)d_in[2 + 2 * i];
    for (int i = 0; i < 7; i++) {
        int total = cfg[i][2] * cfg[i][0] * 72;
        wtrans_kernel<<<(total + 255) / 256, 256>>>(w[i], wH + woff[i], cfg[i][0], cfg[i][1], total);
    }

    run_stack(outputs, wH, bs, pad0, pad1, pad2, pad3, pad4, pad5, pad6, f1, f2, f3, xT);
    run_stack(styles,  wH, bs, pad0, pad1, pad2, pad3, pad4, pad5, pad6, f1, f2, f3, sT);

    initmax_kernel<<<(BATCH * FEATN + 255) / 256, 256>>>(gmax);
    simmax_mma_f16<<<dim3(FEATN / 128, FEATN / 128, BATCH), 256, SIM_SMEM>>>(xT, sT, gmax);
    final_loss_kernel<<<1, 256>>>(gmax, (float*)d_out);
}

// round 14
// speedup vs baseline: 1.5156x; 1.0215x over previous
#include <cuda_runtime.h>
#include <cuda_fp16.h>
#include <cstdint>
#include <math.h>

// ---------------------------------------------------------------------------
// VGG16-block3 features on outputs+styles [4,3,256,256], then
// loss = mean_{b,n} (1 - max_m xn[b,n].sn[b,m]),  C=768, N=M=4096.
//
// Full fp16 datapath (fp32 accumulate) on m16n8k16 MMA, cp.async-pipelined,
// fragment loads via ldmatrix (LDSM). Structure = round-8/13 proven base.
// Activations: zero-padded channel-pair half2 layout [C/2][H+2][W+4]; storage
// pair P=(chunk c, p) holds logical channels (16c+p, 16c+8+p). Weights
// permuted to match. Padded borders rely on .bss zero-init, never written.
// ---------------------------------------------------------------------------

#define BATCH 4
#define FEATC 768
#define FEATN 4096

__device__ __half2 g_pad0[(size_t)BATCH * 8 * 258 * 260];
__device__ __half2 g_pad1[(size_t)BATCH * 32 * 258 * 260];
__device__ __half2 g_pad2[(size_t)BATCH * 32 * 258 * 260];
__device__ __half2 g_pad3[(size_t)BATCH * 32 * 130 * 132];
__device__ __half2 g_pad4[(size_t)BATCH * 64 * 130 * 132];
__device__ __half2 g_pad5[(size_t)BATCH * 64 * 130 * 132];
__device__ __half2 g_pad6[(size_t)BATCH * 64 * 66 * 68];
__device__ __half2 g_f1[(size_t)BATCH * 128 * 66 * 68];
__device__ __half2 g_f2[(size_t)BATCH * 128 * 66 * 68];
__device__ __half2 g_f3[(size_t)BATCH * 128 * 66 * 68];
__device__ __half  g_xT[(size_t)BATCH * FEATN * FEATC];
__device__ __half  g_sT[(size_t)BATCH * FEATN * FEATC];
__device__ __half2 g_wH[870912];
__device__ float   g_maxsim[BATCH * FEATN];

#define MMA_F16(c, a, bfr) \
    asm volatile("mma.sync.aligned.m16n8k16.row.col.f32.f16.f16.f32 " \
        "{%0,%1,%2,%3}, {%4,%5,%6,%7}, {%8,%9}, {%0,%1,%2,%3};" \
        : "+f"((c)[0]), "+f"((c)[1]), "+f"((c)[2]), "+f"((c)[3]) \
        : "r"((a)[0]), "r"((a)[1]), "r"((a)[2]), "r"((a)[3]), \
          "r"((bfr)[0]), "r"((bfr)[1]))

#define LDSM_X4(r0, r1, r2, r3, addr) \
    asm volatile("ldmatrix.sync.aligned.m8n8.x4.shared.b16 {%0,%1,%2,%3}, [%4];" \
        : "=r"(r0), "=r"(r1), "=r"(r2), "=r"(r3) : "r"(addr))
#define LDSM_X2(r0, r1, addr) \
    asm volatile("ldmatrix.sync.aligned.m8n8.x2.shared.b16 {%0,%1}, [%2];" \
        : "=r"(r0), "=r"(r1) : "r"(addr))

__device__ __forceinline__ void cpa16(uint32_t dst, const void* src) {
    asm volatile("cp.async.cg.shared.global [%0], [%1], 16;" :: "r"(dst), "l"(src));
}
#define CPA_COMMIT() asm volatile("cp.async.commit_group;" ::: "memory")
#define CPA_WAIT1()  asm volatile("cp.async.wait_group 1;" ::: "memory")
#define CPA_WAIT0()  asm volatile("cp.async.wait_group 0;" ::: "memory")

// ---------------------------------------------------------------------------
// input normalization -> padded half2 pair layout (pairs (p, p+8); ch>=3 zero)
// ---------------------------------------------------------------------------
__global__ void norm_input_pad_kernel(const float* __restrict__ in, __half2* __restrict__ out) {
    int i = blockIdx.x * blockDim.x + threadIdx.x;
    if (i >= BATCH * 3 * 65536) return;
    int x = i & 255, y = (i >> 8) & 255;
    int c = (i >> 16) % 3, b = i / (3 * 65536);
    const float mean[3] = {0.485f, 0.456f, 0.406f};
    const float stdv[3] = {0.229f, 0.224f, 0.225f};
    float v = (in[i] - mean[c]) / stdv[c];
    out[((size_t)(b * 8 + c) * 258 + 1 + y) * 260 + 1 + x] = __floats2half2_rn(v, 0.f);
}

// ---------------------------------------------------------------------------
// weight transform: w[oc][ic][3x3] -> wH[(c*OC+oc)*72 + t*8 + p]
// (row per (oc,tap) = 16 halves in MMA k-order: half 2p = ch 16c+p, 2p+1 = 16c+8+p)
// ---------------------------------------------------------------------------
__global__ void wtrans_kernel(const float* __restrict__ w, __half2* __restrict__ wH,
                              int OC, int Cin, int total) {
    int i = blockIdx.x * blockDim.x + threadIdx.x;
    if (i >= total) return;
    int within = i % 72;
    int t = within >> 3, p = within & 7;
    int oc = (i / 72) % OC;
    int c = i / (72 * OC);
    int ic0 = 16 * c + p, ic1 = ic0 + 8;
    float v0 = (ic0 < Cin) ? w[((size_t)oc * Cin + ic0) * 9 + t] : 0.f;
    float v1 = (ic1 < Cin) ? w[((size_t)oc * Cin + ic1) * 9 + t] : 0.f;
    wH[i] = __floats2half2_rn(v0, v1);
}

// ---------------------------------------------------------------------------
// fp16 implicit-GEMM 3x3 conv + bias + ReLU, cp.async double-buffered.
// Block 256 thr: 64 oc x 256 px (ROWS x COLS). Warps 2(oc) x 4(px).
// Weights loaded via ldmatrix.x4 (smem stride 76 half2 -> conflict-free rows).
// ---------------------------------------------------------------------------
template <int ROWS, int COLS>
__global__ __launch_bounds__(256, 2)
void conv_mma_f16(const __half2* __restrict__ in, const __half2* __restrict__ wH,
                  const float* __restrict__ bias, __half2* __restrict__ out,
                  int chunks, int OC) {
    constexpr int PW2 = COLS + 4;
    constexpr int PR = ROWS + 2;
    constexpr int ICS2 = (PR * PW2 + 31) / 32 * 32 + 8;
    constexpr int WS_SIZE = 64 * 76;        // half2 units, padded oc-stride 76
    constexpr int PATCH_SIZE = 8 * ICS2;
    constexpr int BUF = WS_SIZE + PATCH_SIZE;
    extern __shared__ __half2 sm[];

    const int tid = threadIdx.x;
    const int wid = tid >> 5, lane = tid & 31;
    const int wm = wid & 1, wn = wid >> 1;
    const int grp = lane >> 2, tg = lane & 3;

    const int b = blockIdx.z;
    const int ocg = blockIdx.y;
    const int y0 = blockIdx.x * ROWS;
    const size_t plane2 = (size_t)(COLS + 2) * PW2;

    const __half2* inB = in + (size_t)b * (chunks * 8) * plane2;
    const uint32_t sm_u32 = (uint32_t)__cvta_generic_to_shared(sm);

    // ldmatrix per-lane mapping: lane -> (matrix, row-in-matrix)
    const int lr = lane & 7;               // row within 8x8 matrix
    const int lmat = lane >> 3;            // 0..3
    const int lrow = ((lmat & 1) << 3) + lr;     // +0 or +8 oc rows
    const int lcol = (lmat >> 1) << 2;           // +0 or +4 half2 cols

    int nb[8];
#pragma unroll
    for (int nf = 0; nf < 8; nf++) {
        int n = wn * 64 + nf * 8 + grp;
        nb[nf] = (n / COLS) * PW2 + (n % COLS);
    }

    float acc[2][8][4];
#pragma unroll
    for (int mf = 0; mf < 2; mf++)
#pragma unroll
        for (int nf = 0; nf < 8; nf++)
#pragma unroll
            for (int k = 0; k < 4; k++) acc[mf][nf][k] = 0.f;

    auto prefetch = [&](int c, int bi) {
        const __half2* wsrc = wH + ((size_t)c * OC + ocg * 64) * 72;
        uint32_t wdst = sm_u32 + (uint32_t)(bi * BUF) * 4;
        for (int id = tid; id < 1152; id += 256) {
            int oc = id / 18, q = id - oc * 18;
            cpa16(wdst + (oc * 76 + q * 4) * 4, wsrc + oc * 72 + q * 4);
        }
        uint32_t pdst = sm_u32 + (uint32_t)(bi * BUF + WS_SIZE) * 4;
        for (int rs = wid; rs < 8 * PR; rs += 8) {
            int pair = rs / PR, row = rs - pair * PR;
            const __half2* src = inB + (size_t)(c * 8 + pair) * plane2 + (size_t)(y0 + row) * PW2;
            uint32_t dst = pdst + (pair * ICS2 + row * PW2) * 4;
            for (int x = lane; x < PW2 / 4; x += 32)
                cpa16(dst + x * 16, src + x * 4);
        }
    };

    prefetch(0, 0);
    CPA_COMMIT();

    for (int c = 0; c < chunks; c++) {
        const int bi = c & 1;
        if (c > 0) __syncthreads();
        if (c + 1 < chunks) {
            prefetch(c + 1, bi ^ 1);
            CPA_COMMIT();
            CPA_WAIT1();
        } else {
            CPA_WAIT0();
        }
        __syncthreads();

        const uint32_t wsbase = sm_u32 + (uint32_t)(bi * BUF) * 4;
        const uint32_t* patchu = (const uint32_t*)(sm + bi * BUF + WS_SIZE);

#pragma unroll
        for (int tap = 0; tap < 9; tap++) {
            const int toff = (tap / 3) * PW2 + (tap % 3);
            uint32_t a[2][4];
#pragma unroll
            for (int mf = 0; mf < 2; mf++) {
                uint32_t aaddr = wsbase +
                    (uint32_t)(((wm * 32 + mf * 16 + lrow) * 76 + tap * 8 + lcol) * 4);
                LDSM_X4(a[mf][0], a[mf][1], a[mf][2], a[mf][3], aaddr);
            }
#pragma unroll
            for (int nf = 0; nf < 8; nf++) {
                uint32_t bf[2];
                bf[0] = patchu[tg * ICS2 + nb[nf] + toff];
                bf[1] = patchu[(tg + 4) * ICS2 + nb[nf] + toff];
                MMA_F16(acc[0][nf], a[0], bf);
                MMA_F16(acc[1][nf], a[1], bf);
            }
        }
    }

    __half2* outB = out + (size_t)b * (OC / 2) * plane2;
#pragma unroll
    for (int mf = 0; mf < 2; mf++) {
        int oc = ocg * 64 + wm * 32 + mf * 16 + grp;
        float bv0 = bias[oc], bv1 = bias[oc + 8];
        int P = (ocg * 4 + wm * 2 + mf) * 8 + grp;
#pragma unroll
        for (int nf = 0; nf < 8; nf++) {
            int n = wn * 64 + nf * 8 + tg * 2;
            int rp = n / COLS, col = n % COLS;
            __half2* o = outB + (size_t)P * plane2 + (size_t)(y0 + 1 + rp) * PW2 + 1 + col;
            o[0] = __floats2half2_rn(fmaxf(acc[mf][nf][0] + bv0, 0.f),
                                     fmaxf(acc[mf][nf][2] + bv1, 0.f));
            o[1] = __floats2half2_rn(fmaxf(acc[mf][nf][1] + bv0, 0.f),
                                     fmaxf(acc[mf][nf][3] + bv1, 0.f));
        }
    }
}

// ---------------------------------------------------------------------------
// 2x2 maxpool on padded half2 buffers
// ---------------------------------------------------------------------------
__global__ void maxpool_pad_kernel(const __half2* __restrict__ in, __half2* __restrict__ out,
                                   int pairs, int H, int W) {
    int Ho = H / 2, Wo = W / 2;
    long total = (long)BATCH * pairs * Ho * Wo;
    long i = (long)blockIdx.x * blockDim.x + threadIdx.x;
    if (i >= total) return;
    int x = (int)(i % Wo);
    long t = i / Wo;
    int y = (int)(t % Ho); t /= Ho;
    int p = (int)(t % pairs);
    int b = (int)(t / pairs);
    const __half2* s = in + ((size_t)(b * pairs + p) * (H + 2) + (1 + 2 * y)) * (W + 4) + 1 + 2 * x;
    __half2 m = __hmax2(__hmax2(s[0], s[1]), __hmax2(s[W + 4], s[W + 5]));
    out[((size_t)(b * pairs + p) * (Ho + 2) + 1 + y) * (Wo + 4) + 1 + x] = m;
}

// ---------------------------------------------------------------------------
// padded f1|f2|f3 [128P][66][68] half2 -> [B][N][384] half2 rows
// ---------------------------------------------------------------------------
__global__ void feat_transpose_kernel(const __half2* __restrict__ f1, const __half2* __restrict__ f2,
                                      const __half2* __restrict__ f3, __half2* __restrict__ out) {
    __shared__ __half2 s[32][33];
    int b = blockIdx.z;
    int Pg = blockIdx.y * 32;
    int n0 = blockIdx.x * 32;
    const __half2* fb = (Pg < 128) ? f1 : (Pg < 256 ? f2 : f3);
    int Pl = Pg & 127;
    int tx = threadIdx.x, ty = threadIdx.y;
    int n = n0 + tx, yy = n >> 6, xx = n & 63;
    size_t base = (size_t)b * 128 * 4488;
#pragma unroll
    for (int i = 0; i < 4; i++)
        s[ty + 8 * i][tx] = fb[base + (size_t)(Pl + ty + 8 * i) * 4488 + (1 + yy) * 68 + 1 + xx];
    __syncthreads();
#pragma unroll
    for (int i = 0; i < 4; i++)
        out[((size_t)b * FEATN + n0 + ty + 8 * i) * 384 + Pg + tx] = s[tx][ty + 8 * i];
}

// ---------------------------------------------------------------------------
// row L2-normalize half rows [B*N][768] in place; warp per row, fp32 math
// ---------------------------------------------------------------------------
__global__ __launch_bounds__(256)
void rownorm_rows_kernel(__half2* __restrict__ f) {
    int row = blockIdx.x * 8 + (threadIdx.x >> 5);
    int lane = threadIdx.x & 31;
    __half2* p = f + (size_t)row * 384;
    float2 v[12];
    float ssq = 0.f;
#pragma unroll
    for (int k = 0; k < 12; k++) {
        v[k] = __half22float2(p[k * 32 + lane]);
        ssq = fmaf(v[k].x, v[k].x, fmaf(v[k].y, v[k].y, ssq));
    }
#pragma unroll
    for (int st = 16; st > 0; st >>= 1)
        ssq += __shfl_xor_sync(0xffffffff, ssq, st);
    float inv = 1.0f / (sqrtf(ssq) + 1e-8f);
#pragma unroll
    for (int k = 0; k < 12; k++)
        p[k * 32 + lane] = __floats2half2_rn(v[k].x * inv, v[k].y * inv);
}

__global__ void initmax_kernel(float* __restrict__ g) {
    int i = blockIdx.x * blockDim.x + threadIdx.x;
    if (i < BATCH * FEATN) g[i] = 0.f;
}

// ---------------------------------------------------------------------------
// fp16 mma sim + row-max, cp.async double-buffered, ldmatrix fragment loads.
// Block 128x128, warps 2x4 (64x32), K-chunk 64 (32 half2), 12 chunks.
// ---------------------------------------------------------------------------
#define SIM_TILE 4608

__global__ __launch_bounds__(256, 2)
void simmax_mma_f16(const __half* __restrict__ xT, const __half* __restrict__ sT,
                    float* __restrict__ gmax) {
    extern __shared__ __half2 sm[];

    const int b = blockIdx.z;
    const int nbase = blockIdx.y * 128;
    const int mbase = blockIdx.x * 128;
    const int tid = threadIdx.x;
    const int wid = tid >> 5, lane = tid & 31;
    const int wm = wid & 1, wn = wid >> 1;
    const int grp = lane >> 2, tg = lane & 3;

    const __half2* xb2 = (const __half2*)xT + ((size_t)b * FEATN + nbase) * 384;
    const __half2* sp2 = (const __half2*)sT + ((size_t)b * FEATN + mbase) * 384;
    const uint32_t sm_u32 = (uint32_t)__cvta_generic_to_shared(sm);

    // ldmatrix per-lane mapping
    const int lr = lane & 7;
    const int lmat = lane >> 3;                  // 0..3
    const int lrowA = ((lmat & 1) << 3) + lr;    // A: +0/+8 rows
    const int lcolA = (lmat >> 1) << 2;          // A: +0/+4 half2 cols
    const int lrowB = lr;                        // B: rows 0..7
    const int lcolB = (lmat & 1) << 2;           // B: matrix0 col+0, matrix1 col+4

    float acc[4][4][4];
#pragma unroll
    for (int mf = 0; mf < 4; mf++)
#pragma unroll
        for (int nf = 0; nf < 4; nf++)
#pragma unroll
            for (int k = 0; k < 4; k++) acc[mf][nf][k] = 0.f;

    auto prefetch = [&](int chunk, int bi) {
        const int kc2 = chunk * 32;
        uint32_t abase = sm_u32 + (uint32_t)(bi * 2 * SIM_TILE) * 4;
        uint32_t bbase = abase + SIM_TILE * 4;
#pragma unroll
        for (int i = 0; i < 4; i++) {
            int id = tid + i * 256;
            int r = id >> 3, q = (id & 7) * 4;
            cpa16(abase + (r * 36 + q) * 4, xb2 + (size_t)r * 384 + kc2 + q);
            cpa16(bbase + (r * 36 + q) * 4, sp2 + (size_t)r * 384 + kc2 + q);
        }
    };

    prefetch(0, 0);
    CPA_COMMIT();

    for (int chunk = 0; chunk < 12; chunk++) {
        const int bi = chunk & 1;
        if (chunk > 0) __syncthreads();
        if (chunk + 1 < 12) {
            prefetch(chunk + 1, bi ^ 1);
            CPA_COMMIT();
            CPA_WAIT1();
        } else {
            CPA_WAIT0();
        }
        __syncthreads();

        const uint32_t abase = sm_u32 + (uint32_t)(bi * 2 * SIM_TILE) * 4;
        const uint32_t bbase = abase + (uint32_t)SIM_TILE * 4;

#pragma unroll
        for (int ks = 0; ks < 4; ks++) {
            const int kk = ks * 8;
            uint32_t a[4][4];
#pragma unroll
            for (int mf = 0; mf < 4; mf++) {
                uint32_t aaddr = abase +
                    (uint32_t)(((wm * 64 + mf * 16 + lrowA) * 36 + kk + lcolA) * 4);
                LDSM_X4(a[mf][0], a[mf][1], a[mf][2], a[mf][3], aaddr);
            }
#pragma unroll
            for (int nf = 0; nf < 4; nf++) {
                uint32_t bf[2];
                uint32_t baddr = bbase +
                    (uint32_t)(((wn * 32 + nf * 8 + lrowB) * 36 + kk + lcolB) * 4);
                LDSM_X2(bf[0], bf[1], baddr);
                MMA_F16(acc[0][nf], a[0], bf);
                MMA_F16(acc[1][nf], a[1], bf);
                MMA_F16(acc[2][nf], a[2], bf);
                MMA_F16(acc[3][nf], a[3], bf);
            }
        }
    }

#pragma unroll
    for (int mf = 0; mf < 4; mf++) {
        float r0 = 0.f, r1 = 0.f;
#pragma unroll
        for (int nf = 0; nf < 4; nf++) {
            r0 = fmaxf(r0, fmaxf(acc[mf][nf][0], acc[mf][nf][1]));
            r1 = fmaxf(r1, fmaxf(acc[mf][nf][2], acc[mf][nf][3]));
        }
        r0 = fmaxf(r0, __shfl_xor_sync(0xffffffff, r0, 1));
        r0 = fmaxf(r0, __shfl_xor_sync(0xffffffff, r0, 2));
        r1 = fmaxf(r1, __shfl_xor_sync(0xffffffff, r1, 1));
        r1 = fmaxf(r1, __shfl_xor_sync(0xffffffff, r1, 2));
        if (tg == 0) {
            int row = nbase + wm * 64 + mf * 16 + grp;
            atomicMax((int*)&gmax[(size_t)b * FEATN + row], __float_as_int(r0));
            atomicMax((int*)&gmax[(size_t)b * FEATN + row + 8], __float_as_int(r1));
        }
    }
}

// ---------------------------------------------------------------------------
// final reduction
// ---------------------------------------------------------------------------
__global__ void final_loss_kernel(const float* __restrict__ gmax, float* __restrict__ out) {
    __shared__ double sm[256];
    double s = 0.0;
    for (int i = threadIdx.x; i < BATCH * FEATN; i += 256)
        s += 1.0 - (double)gmax[i];
    sm[threadIdx.x] = s;
    __syncthreads();
    for (int st = 128; st > 0; st >>= 1) {
        if (threadIdx.x < st) sm[threadIdx.x] += sm[threadIdx.x + st];
        __syncthreads();
    }
    if (threadIdx.x == 0)
        out[0] = (float)(sm[0] / (double)(BATCH * FEATN));
}

// ---------------------------------------------------------------------------
// host orchestration
// ---------------------------------------------------------------------------
static constexpr int conv_smem(int R, int C) {
    int PW2 = C + 4, PR = R + 2;
    int ICS2 = (PR * PW2 + 31) / 32 * 32 + 8;
    return 2 * (64 * 76 + 8 * ICS2) * 4;
}
#define CS_R1 conv_smem(1, 256)
#define CS_R2 conv_smem(2, 128)
#define CS_R4 conv_smem(4, 64)
#define SIM_SMEM (4 * SIM_TILE * 4)

static void run_stack(const float* img, __half2* wH, const float* const* bs,
                      __half2* pad0, __half2* pad1, __half2* pad2, __half2* pad3,
                      __half2* pad4, __half2* pad5, __half2* pad6,
                      __half2* f1, __half2* f2, __half2* f3, __half* featT) {
    const long o0 = 0, o1 = 4608, o2 = 23040, o3 = 59904,
               o4 = 133632, o5 = 281088, o6 = 576000;

    norm_input_pad_kernel<<<(BATCH * 3 * 65536 + 255) / 256, 256>>>(img, pad0);

    conv_mma_f16<1, 256><<<dim3(256, 1, BATCH), 256, CS_R1>>>(pad0, wH + o0, bs[0], pad1, 1, 64);
    conv_mma_f16<1, 256><<<dim3(256, 1, BATCH), 256, CS_R1>>>(pad1, wH + o1, bs[1], pad2, 4, 64);
    {
        long total = (long)BATCH * 32 * 128 * 128;
        maxpool_pad_kernel<<<(unsigned)((total + 255) / 256), 256>>>(pad2, pad3, 32, 256, 256);
    }
    conv_mma_f16<2, 128><<<dim3(64, 2, BATCH), 256, CS_R2>>>(pad3, wH + o2, bs[2], pad4, 4, 128);
    conv_mma_f16<2, 128><<<dim3(64, 2, BATCH), 256, CS_R2>>>(pad4, wH + o3, bs[3], pad5, 8, 128);
    {
        long total = (long)BATCH * 64 * 64 * 64;
        maxpool_pad_kernel<<<(unsigned)((total + 255) / 256), 256>>>(pad5, pad6, 64, 128, 128);
    }
    conv_mma_f16<4, 64><<<dim3(16, 4, BATCH), 256, CS_R4>>>(pad6, wH + o4, bs[4], f1, 8, 256);
    conv_mma_f16<4, 64><<<dim3(16, 4, BATCH), 256, CS_R4>>>(f1, wH + o5, bs[5], f2, 16, 256);
    conv_mma_f16<4, 64><<<dim3(16, 4, BATCH), 256, CS_R4>>>(f2, wH + o6, bs[6], f3, 16, 256);

    feat_transpose_kernel<<<dim3(128, 12, BATCH), dim3(32, 8)>>>(f1, f2, f3, (__half2*)featT);
    rownorm_rows_kernel<<<BATCH * FEATN / 8, 256>>>((__half2*)featT);
}

extern "C" void kernel_launch(void* const* d_in, const int* in_sizes, int n_in,
                              void* d_out, int out_size) {
    (void)in_sizes; (void)n_in; (void)out_size;

    __half2 *pad0, *pad1, *pad2, *pad3, *pad4, *pad5, *pad6, *f1, *f2, *f3, *wH;
    __half *xT, *sT;
    float *gmax;
    cudaGetSymbolAddress((void**)&pad0, g_pad0);
    cudaGetSymbolAddress((void**)&pad1, g_pad1);
    cudaGetSymbolAddress((void**)&pad2, g_pad2);
    cudaGetSymbolAddress((void**)&pad3, g_pad3);
    cudaGetSymbolAddress((void**)&pad4, g_pad4);
    cudaGetSymbolAddress((void**)&pad5, g_pad5);
    cudaGetSymbolAddress((void**)&pad6, g_pad6);
    cudaGetSymbolAddress((void**)&f1, g_f1);
    cudaGetSymbolAddress((void**)&f2, g_f2);
    cudaGetSymbolAddress((void**)&f3, g_f3);
    cudaGetSymbolAddress((void**)&xT, g_xT);
    cudaGetSymbolAddress((void**)&sT, g_sT);
    cudaGetSymbolAddress((void**)&wH, g_wH);
    cudaGetSymbolAddress((void**)&gmax, g_maxsim);

    cudaFuncSetAttribute(conv_mma_f16<1, 256>, cudaFuncAttributeMaxDynamicSharedMemorySize, CS_R1);
    cudaFuncSetAttribute(conv_mma_f16<2, 128>, cudaFuncAttributeMaxDynamicSharedMemorySize, CS_R2);
    cudaFuncSetAttribute(conv_mma_f16<4, 64>,  cudaFuncAttributeMaxDynamicSharedMemorySize, CS_R4);
    cudaFuncSetAttribute(simmax_mma_f16, cudaFuncAttributeMaxDynamicSharedMemorySize, SIM_SMEM);

    const float* outputs = (const float*)d_in[0];
    const float* styles  = (const float*)d_in[1];
    const float* bs[7];
    for (int i = 0; i < 7; i++) bs[i] = (const float*)d_in[3 + 2 * i];

    const int cfg[7][3] = {{64,3,1},{64,64,4},{128,64,4},{128,128,8},
                           {256,128,8},{256,256,16},{256,256,16}};
    const long woff[7] = {0, 4608, 23040, 59904, 133632, 281088, 576000};
    const float* w[7];
    for (int i = 0; i < 7; i++) w[i] = (const float*)d_in[2 + 2 * i];
    for (int i = 0; i < 7; i++) {
        int total = cfg[i][2] * cfg[i][0] * 72;
        wtrans_kernel<<<(total + 255) / 256, 256>>>(w[i], wH + woff[i], cfg[i][0], cfg[i][1], total);
    }

    run_stack(outputs, wH, bs, pad0, pad1, pad2, pad3, pad4, pad5, pad6, f1, f2, f3, xT);
    run_stack(styles,  wH, bs, pad0, pad1, pad2, pad3, pad4, pad5, pad6, f1, f2, f3, sT);

    initmax_kernel<<<(BATCH * FEATN + 255) / 256, 256>>>(gmax);
    simmax_mma_f16<<<dim3(FEATN / 128, FEATN / 128, BATCH), 256, SIM_SMEM>>>(xT, sT, gmax);
    final_loss_kernel<<<1, 256>>>(gmax, (float*)d_out);
}

// round 15
// speedup vs baseline: 1.5203x; 1.0031x over previous
#include <cuda_runtime.h>
#include <cuda_fp16.h>
#include <cstdint>
#include <math.h>

// ---------------------------------------------------------------------------
// VGG16-block3 features on outputs+styles [4,3,256,256], then
// loss = mean_{b,n} (1 - max_m xn[b,n].sn[b,m]),  C=768, N=M=4096.
//
// Full fp16 datapath (fp32 accumulate) on m16n8k16 MMA, cp.async-pipelined,
// fragment loads via ldmatrix (LDSM). Structure = round-14 proven base.
// This round: fused weight transform (1 launch) + fused transpose+rownorm.
// Activations: zero-padded channel-pair half2 layout [C/2][H+2][W+4]; storage
// pair P=(chunk c, p) holds logical channels (16c+p, 16c+8+p). Weights
// permuted to match. Padded borders rely on .bss zero-init, never written.
// ---------------------------------------------------------------------------

#define BATCH 4
#define FEATC 768
#define FEATN 4096

__device__ __half2 g_pad0[(size_t)BATCH * 8 * 258 * 260];
__device__ __half2 g_pad1[(size_t)BATCH * 32 * 258 * 260];
__device__ __half2 g_pad2[(size_t)BATCH * 32 * 258 * 260];
__device__ __half2 g_pad3[(size_t)BATCH * 32 * 130 * 132];
__device__ __half2 g_pad4[(size_t)BATCH * 64 * 130 * 132];
__device__ __half2 g_pad5[(size_t)BATCH * 64 * 130 * 132];
__device__ __half2 g_pad6[(size_t)BATCH * 64 * 66 * 68];
__device__ __half2 g_f1[(size_t)BATCH * 128 * 66 * 68];
__device__ __half2 g_f2[(size_t)BATCH * 128 * 66 * 68];
__device__ __half2 g_f3[(size_t)BATCH * 128 * 66 * 68];
__device__ __half  g_xT[(size_t)BATCH * FEATN * FEATC];
__device__ __half  g_sT[(size_t)BATCH * FEATN * FEATC];
__device__ __half2 g_wH[870912];
__device__ float   g_maxsim[BATCH * FEATN];

#define MMA_F16(c, a, bfr) \
    asm volatile("mma.sync.aligned.m16n8k16.row.col.f32.f16.f16.f32 " \
        "{%0,%1,%2,%3}, {%4,%5,%6,%7}, {%8,%9}, {%0,%1,%2,%3};" \
        : "+f"((c)[0]), "+f"((c)[1]), "+f"((c)[2]), "+f"((c)[3]) \
        : "r"((a)[0]), "r"((a)[1]), "r"((a)[2]), "r"((a)[3]), \
          "r"((bfr)[0]), "r"((bfr)[1]))

#define LDSM_X4(r0, r1, r2, r3, addr) \
    asm volatile("ldmatrix.sync.aligned.m8n8.x4.shared.b16 {%0,%1,%2,%3}, [%4];" \
        : "=r"(r0), "=r"(r1), "=r"(r2), "=r"(r3) : "r"(addr))
#define LDSM_X2(r0, r1, addr) \
    asm volatile("ldmatrix.sync.aligned.m8n8.x2.shared.b16 {%0,%1}, [%2];" \
        : "=r"(r0), "=r"(r1) : "r"(addr))

__device__ __forceinline__ void cpa16(uint32_t dst, const void* src) {
    asm volatile("cp.async.cg.shared.global [%0], [%1], 16;" :: "r"(dst), "l"(src));
}
#define CPA_COMMIT() asm volatile("cp.async.commit_group;" ::: "memory")
#define CPA_WAIT1()  asm volatile("cp.async.wait_group 1;" ::: "memory")
#define CPA_WAIT0()  asm volatile("cp.async.wait_group 0;" ::: "memory")

// ---------------------------------------------------------------------------
// input normalization -> padded half2 pair layout (pairs (p, p+8); ch>=3 zero)
// ---------------------------------------------------------------------------
__global__ void norm_input_pad_kernel(const float* __restrict__ in, __half2* __restrict__ out) {
    int i = blockIdx.x * blockDim.x + threadIdx.x;
    if (i >= BATCH * 3 * 65536) return;
    int x = i & 255, y = (i >> 8) & 255;
    int c = (i >> 16) % 3, b = i / (3 * 65536);
    const float mean[3] = {0.485f, 0.456f, 0.406f};
    const float stdv[3] = {0.229f, 0.224f, 0.225f};
    float v = (in[i] - mean[c]) / stdv[c];
    out[((size_t)(b * 8 + c) * 258 + 1 + y) * 260 + 1 + x] = __floats2half2_rn(v, 0.f);
}

// ---------------------------------------------------------------------------
// fused weight transform for all 7 layers (single launch):
// w[oc][ic][3x3] -> wH[seg + (c*OC+oc)*72 + t*8 + p]
// ---------------------------------------------------------------------------
__global__ void wtrans_all_kernel(const float* __restrict__ w0, const float* __restrict__ w1,
                                  const float* __restrict__ w2, const float* __restrict__ w3,
                                  const float* __restrict__ w4, const float* __restrict__ w5,
                                  const float* __restrict__ w6, __half2* __restrict__ wH) {
    const int i = blockIdx.x * blockDim.x + threadIdx.x;
    if (i >= 870912) return;
    const int ends[7] = {4608, 23040, 59904, 133632, 281088, 576000, 870912};
    const int OCt[7] = {64, 64, 128, 128, 256, 256, 256};
    const int Cint[7] = {3, 64, 64, 128, 128, 256, 256};
    int L = 0;
    while (i >= ends[L]) L++;
    int base = (L == 0) ? 0 : ends[L - 1];
    const float* wsrc[7] = {w0, w1, w2, w3, w4, w5, w6};
    const float* w = wsrc[L];
    int OC = OCt[L], Cin = Cint[L];
    int j = i - base;
    int within = j % 72;
    int t = within >> 3, p = within & 7;
    int oc = (j / 72) % OC;
    int c = j / (72 * OC);
    int ic0 = 16 * c + p, ic1 = ic0 + 8;
    float v0 = (ic0 < Cin) ? w[((size_t)oc * Cin + ic0) * 9 + t] : 0.f;
    float v1 = (ic1 < Cin) ? w[((size_t)oc * Cin + ic1) * 9 + t] : 0.f;
    wH[i] = __floats2half2_rn(v0, v1);
}

// ---------------------------------------------------------------------------
// fp16 implicit-GEMM 3x3 conv + bias + ReLU, cp.async double-buffered.
// Block 256 thr: 64 oc x 256 px (ROWS x COLS). Warps 2(oc) x 4(px).
// Weights loaded via ldmatrix.x4 (smem stride 76 half2 -> conflict-free rows).
// ---------------------------------------------------------------------------
template <int ROWS, int COLS>
__global__ __launch_bounds__(256, 2)
void conv_mma_f16(const __half2* __restrict__ in, const __half2* __restrict__ wH,
                  const float* __restrict__ bias, __half2* __restrict__ out,
                  int chunks, int OC) {
    constexpr int PW2 = COLS + 4;
    constexpr int PR = ROWS + 2;
    constexpr int ICS2 = (PR * PW2 + 31) / 32 * 32 + 8;
    constexpr int WS_SIZE = 64 * 76;
    constexpr int PATCH_SIZE = 8 * ICS2;
    constexpr int BUF = WS_SIZE + PATCH_SIZE;
    extern __shared__ __half2 sm[];

    const int tid = threadIdx.x;
    const int wid = tid >> 5, lane = tid & 31;
    const int wm = wid & 1, wn = wid >> 1;
    const int grp = lane >> 2, tg = lane & 3;

    const int b = blockIdx.z;
    const int ocg = blockIdx.y;
    const int y0 = blockIdx.x * ROWS;
    const size_t plane2 = (size_t)(COLS + 2) * PW2;

    const __half2* inB = in + (size_t)b * (chunks * 8) * plane2;
    const uint32_t sm_u32 = (uint32_t)__cvta_generic_to_shared(sm);

    const int lr = lane & 7;
    const int lmat = lane >> 3;
    const int lrow = ((lmat & 1) << 3) + lr;
    const int lcol = (lmat >> 1) << 2;

    int nb[8];
#pragma unroll
    for (int nf = 0; nf < 8; nf++) {
        int n = wn * 64 + nf * 8 + grp;
        nb[nf] = (n / COLS) * PW2 + (n % COLS);
    }

    float acc[2][8][4];
#pragma unroll
    for (int mf = 0; mf < 2; mf++)
#pragma unroll
        for (int nf = 0; nf < 8; nf++)
#pragma unroll
            for (int k = 0; k < 4; k++) acc[mf][nf][k] = 0.f;

    auto prefetch = [&](int c, int bi) {
        const __half2* wsrc = wH + ((size_t)c * OC + ocg * 64) * 72;
        uint32_t wdst = sm_u32 + (uint32_t)(bi * BUF) * 4;
        for (int id = tid; id < 1152; id += 256) {
            int oc = id / 18, q = id - oc * 18;
            cpa16(wdst + (oc * 76 + q * 4) * 4, wsrc + oc * 72 + q * 4);
        }
        uint32_t pdst = sm_u32 + (uint32_t)(bi * BUF + WS_SIZE) * 4;
        for (int rs = wid; rs < 8 * PR; rs += 8) {
            int pair = rs / PR, row = rs - pair * PR;
            const __half2* src = inB + (size_t)(c * 8 + pair) * plane2 + (size_t)(y0 + row) * PW2;
            uint32_t dst = pdst + (pair * ICS2 + row * PW2) * 4;
            for (int x = lane; x < PW2 / 4; x += 32)
                cpa16(dst + x * 16, src + x * 4);
        }
    };

    prefetch(0, 0);
    CPA_COMMIT();

    for (int c = 0; c < chunks; c++) {
        const int bi = c & 1;
        if (c > 0) __syncthreads();
        if (c + 1 < chunks) {
            prefetch(c + 1, bi ^ 1);
            CPA_COMMIT();
            CPA_WAIT1();
        } else {
            CPA_WAIT0();
        }
        __syncthreads();

        const uint32_t wsbase = sm_u32 + (uint32_t)(bi * BUF) * 4;
        const uint32_t* patchu = (const uint32_t*)(sm + bi * BUF + WS_SIZE);

#pragma unroll
        for (int tap = 0; tap < 9; tap++) {
            const int toff = (tap / 3) * PW2 + (tap % 3);
            uint32_t a[2][4];
#pragma unroll
            for (int mf = 0; mf < 2; mf++) {
                uint32_t aaddr = wsbase +
                    (uint32_t)(((wm * 32 + mf * 16 + lrow) * 76 + tap * 8 + lcol) * 4);
                LDSM_X4(a[mf][0], a[mf][1], a[mf][2], a[mf][3], aaddr);
            }
#pragma unroll
            for (int nf = 0; nf < 8; nf++) {
                uint32_t bf[2];
                bf[0] = patchu[tg * ICS2 + nb[nf] + toff];
                bf[1] = patchu[(tg + 4) * ICS2 + nb[nf] + toff];
                MMA_F16(acc[0][nf], a[0], bf);
                MMA_F16(acc[1][nf], a[1], bf);
            }
        }
    }

    __half2* outB = out + (size_t)b * (OC / 2) * plane2;
#pragma unroll
    for (int mf = 0; mf < 2; mf++) {
        int oc = ocg * 64 + wm * 32 + mf * 16 + grp;
        float bv0 = bias[oc], bv1 = bias[oc + 8];
        int P = (ocg * 4 + wm * 2 + mf) * 8 + grp;
#pragma unroll
        for (int nf = 0; nf < 8; nf++) {
            int n = wn * 64 + nf * 8 + tg * 2;
            int rp = n / COLS, col = n % COLS;
            __half2* o = outB + (size_t)P * plane2 + (size_t)(y0 + 1 + rp) * PW2 + 1 + col;
            o[0] = __floats2half2_rn(fmaxf(acc[mf][nf][0] + bv0, 0.f),
                                     fmaxf(acc[mf][nf][2] + bv1, 0.f));
            o[1] = __floats2half2_rn(fmaxf(acc[mf][nf][1] + bv0, 0.f),
                                     fmaxf(acc[mf][nf][3] + bv1, 0.f));
        }
    }
}

// ---------------------------------------------------------------------------
// 2x2 maxpool on padded half2 buffers
// ---------------------------------------------------------------------------
__global__ void maxpool_pad_kernel(const __half2* __restrict__ in, __half2* __restrict__ out,
                                   int pairs, int H, int W) {
    int Ho = H / 2, Wo = W / 2;
    long total = (long)BATCH * pairs * Ho * Wo;
    long i = (long)blockIdx.x * blockDim.x + threadIdx.x;
    if (i >= total) return;
    int x = (int)(i % Wo);
    long t = i / Wo;
    int y = (int)(t % Ho); t /= Ho;
    int p = (int)(t % pairs);
    int b = (int)(t / pairs);
    const __half2* s = in + ((size_t)(b * pairs + p) * (H + 2) + (1 + 2 * y)) * (W + 4) + 1 + 2 * x;
    __half2 m = __hmax2(__hmax2(s[0], s[1]), __hmax2(s[W + 4], s[W + 5]));
    out[((size_t)(b * pairs + p) * (Ho + 2) + 1 + y) * (Wo + 4) + 1 + x] = m;
}

// ---------------------------------------------------------------------------
// FUSED transpose + L2-normalize:
// padded f1|f2|f3 [128P][66][68] half2 -> normalized [B][N][384] half2 rows.
// Block = 32 n-values; smem tile [32 n][385 P-stride] (stride 385 ≡ 1 mod 32
// -> transposed writes AND row reads conflict-free). Per-row ssq via 8-lane
// partial sums + shuffle reduce; scale applied on the single coalesced write.
// ---------------------------------------------------------------------------
#define TN_SMEM (32 * 385 * 4 + 128)

__global__ __launch_bounds__(256)
void feat_transnorm_kernel(const __half2* __restrict__ f1, const __half2* __restrict__ f2,
                           const __half2* __restrict__ f3, __half2* __restrict__ out) {
    extern __shared__ __half2 smn[];             // [32][385]
    float* sInv = (float*)(smn + 32 * 385);
    const int b = blockIdx.y;
    const int n0 = blockIdx.x * 32;
    const int tx = threadIdx.x, ty = threadIdx.y;   // 32 x 8
    const int n = n0 + tx, yy = n >> 6, xx = n & 63;
    const size_t base = (size_t)b * 128 * 4488;
    const size_t off = base + (size_t)(1 + yy) * 68 + 1 + xx;

    // gather all 384 channel-pairs for these 32 spatial locations
#pragma unroll
    for (int Pg0 = 0; Pg0 < 12; Pg0++) {
        const int Pg = Pg0 * 32;
        const __half2* fb = (Pg < 128) ? f1 : (Pg < 256 ? f2 : f3);
        const int Pl = Pg & 127;
#pragma unroll
        for (int i = 0; i < 4; i++) {
            int c = ty + 8 * i;
            smn[tx * 385 + Pg + c] = fb[off + (size_t)(Pl + c) * 4488];
        }
    }
    __syncthreads();

    // per-row inverse norm (8 threads per row)
    {
        int t = ty * 32 + tx;
        int r = t >> 3, j = t & 7;
        float ssq = 0.f;
#pragma unroll
        for (int k = 0; k < 48; k++) {
            float2 v = __half22float2(smn[r * 385 + j + 8 * k]);
            ssq = fmaf(v.x, v.x, fmaf(v.y, v.y, ssq));
        }
        ssq += __shfl_xor_sync(0xffffffff, ssq, 1);
        ssq += __shfl_xor_sync(0xffffffff, ssq, 2);
        ssq += __shfl_xor_sync(0xffffffff, ssq, 4);
        if (j == 0) sInv[r] = 1.0f / (sqrtf(ssq) + 1e-8f);
    }
    __syncthreads();

    // scaled coalesced write of [n][384] rows
#pragma unroll
    for (int i = 0; i < 4; i++) {
        int row = ty + 8 * i;
        float inv = sInv[row];
        __half2* orow = out + ((size_t)b * FEATN + n0 + row) * 384;
#pragma unroll
        for (int k = 0; k < 12; k++) {
            float2 v = __half22float2(smn[row * 385 + k * 32 + tx]);
            orow[k * 32 + tx] = __floats2half2_rn(v.x * inv, v.y * inv);
        }
    }
}

__global__ void initmax_kernel(float* __restrict__ g) {
    int i = blockIdx.x * blockDim.x + threadIdx.x;
    if (i < BATCH * FEATN) g[i] = 0.f;
}

// ---------------------------------------------------------------------------
// fp16 mma sim + row-max, cp.async double-buffered, ldmatrix fragment loads.
// Block 128x128, warps 2x4 (64x32), K-chunk 64 (32 half2), 12 chunks.
// ---------------------------------------------------------------------------
#define SIM_TILE 4608

__global__ __launch_bounds__(256, 2)
void simmax_mma_f16(const __half* __restrict__ xT, const __half* __restrict__ sT,
                    float* __restrict__ gmax) {
    extern __shared__ __half2 sm[];

    const int b = blockIdx.z;
    const int nbase = blockIdx.y * 128;
    const int mbase = blockIdx.x * 128;
    const int tid = threadIdx.x;
    const int wid = tid >> 5, lane = tid & 31;
    const int wm = wid & 1, wn = wid >> 1;
    const int grp = lane >> 2, tg = lane & 3;

    const __half2* xb2 = (const __half2*)xT + ((size_t)b * FEATN + nbase) * 384;
    const __half2* sp2 = (const __half2*)sT + ((size_t)b * FEATN + mbase) * 384;
    const uint32_t sm_u32 = (uint32_t)__cvta_generic_to_shared(sm);

    const int lr = lane & 7;
    const int lmat = lane >> 3;
    const int lrowA = ((lmat & 1) << 3) + lr;
    const int lcolA = (lmat >> 1) << 2;
    const int lrowB = lr;
    const int lcolB = (lmat & 1) << 2;

    float acc[4][4][4];
#pragma unroll
    for (int mf = 0; mf < 4; mf++)
#pragma unroll
        for (int nf = 0; nf < 4; nf++)
#pragma unroll
            for (int k = 0; k < 4; k++) acc[mf][nf][k] = 0.f;

    auto prefetch = [&](int chunk, int bi) {
        const int kc2 = chunk * 32;
        uint32_t abase = sm_u32 + (uint32_t)(bi * 2 * SIM_TILE) * 4;
        uint32_t bbase = abase + SIM_TILE * 4;
#pragma unroll
        for (int i = 0; i < 4; i++) {
            int id = tid + i * 256;
            int r = id >> 3, q = (id & 7) * 4;
            cpa16(abase + (r * 36 + q) * 4, xb2 + (size_t)r * 384 + kc2 + q);
            cpa16(bbase + (r * 36 + q) * 4, sp2 + (size_t)r * 384 + kc2 + q);
        }
    };

    prefetch(0, 0);
    CPA_COMMIT();

    for (int chunk = 0; chunk < 12; chunk++) {
        const int bi = chunk & 1;
        if (chunk > 0) __syncthreads();
        if (chunk + 1 < 12) {
            prefetch(chunk + 1, bi ^ 1);
            CPA_COMMIT();
            CPA_WAIT1();
        } else {
            CPA_WAIT0();
        }
        __syncthreads();

        const uint32_t abase = sm_u32 + (uint32_t)(bi * 2 * SIM_TILE) * 4;
        const uint32_t bbase = abase + (uint32_t)SIM_TILE * 4;

#pragma unroll
        for (int ks = 0; ks < 4; ks++) {
            const int kk = ks * 8;
            uint32_t a[4][4];
#pragma unroll
            for (int mf = 0; mf < 4; mf++) {
                uint32_t aaddr = abase +
                    (uint32_t)(((wm * 64 + mf * 16 + lrowA) * 36 + kk + lcolA) * 4);
                LDSM_X4(a[mf][0], a[mf][1], a[mf][2], a[mf][3], aaddr);
            }
#pragma unroll
            for (int nf = 0; nf < 4; nf++) {
                uint32_t bf[2];
                uint32_t baddr = bbase +
                    (uint32_t)(((wn * 32 + nf * 8 + lrowB) * 36 + kk + lcolB) * 4);
                LDSM_X2(bf[0], bf[1], baddr);
                MMA_F16(acc[0][nf], a[0], bf);
                MMA_F16(acc[1][nf], a[1], bf);
                MMA_F16(acc[2][nf], a[2], bf);
                MMA_F16(acc[3][nf], a[3], bf);
            }
        }
    }

#pragma unroll
    for (int mf = 0; mf < 4; mf++) {
        float r0 = 0.f, r1 = 0.f;
#pragma unroll
        for (int nf = 0; nf < 4; nf++) {
            r0 = fmaxf(r0, fmaxf(acc[mf][nf][0], acc[mf][nf][1]));
            r1 = fmaxf(r1, fmaxf(acc[mf][nf][2], acc[mf][nf][3]));
        }
        r0 = fmaxf(r0, __shfl_xor_sync(0xffffffff, r0, 1));
        r0 = fmaxf(r0, __shfl_xor_sync(0xffffffff, r0, 2));
        r1 = fmaxf(r1, __shfl_xor_sync(0xffffffff, r1, 1));
        r1 = fmaxf(r1, __shfl_xor_sync(0xffffffff, r1, 2));
        if (tg == 0) {
            int row = nbase + wm * 64 + mf * 16 + grp;
            atomicMax((int*)&gmax[(size_t)b * FEATN + row], __float_as_int(r0));
            atomicMax((int*)&gmax[(size_t)b * FEATN + row + 8], __float_as_int(r1));
        }
    }
}

// ---------------------------------------------------------------------------
// final reduction
// ---------------------------------------------------------------------------
__global__ void final_loss_kernel(const float* __restrict__ gmax, float* __restrict__ out) {
    __shared__ double sm[256];
    double s = 0.0;
    for (int i = threadIdx.x; i < BATCH * FEATN; i += 256)
        s += 1.0 - (double)gmax[i];
    sm[threadIdx.x] = s;
    __syncthreads();
    for (int st = 128; st > 0; st >>= 1) {
        if (threadIdx.x < st) sm[threadIdx.x] += sm[threadIdx.x + st];
        __syncthreads();
    }
    if (threadIdx.x == 0)
        out[0] = (float)(sm[0] / (double)(BATCH * FEATN));
}

// ---------------------------------------------------------------------------
// host orchestration
// ---------------------------------------------------------------------------
static constexpr int conv_smem(int R, int C) {
    int PW2 = C + 4, PR = R + 2;
    int ICS2 = (PR * PW2 + 31) / 32 * 32 + 8;
    return 2 * (64 * 76 + 8 * ICS2) * 4;
}
#define CS_R1 conv_smem(1, 256)
#define CS_R2 conv_smem(2, 128)
#define CS_R4 conv_smem(4, 64)
#define SIM_SMEM (4 * SIM_TILE * 4)

static void run_stack(const float* img, __half2* wH, const float* const* bs,
                      __half2* pad0, __half2* pad1, __half2* pad2, __half2* pad3,
                      __half2* pad4, __half2* pad5, __half2* pad6,
                      __half2* f1, __half2* f2, __half2* f3, __half* featT) {
    const long o0 = 0, o1 = 4608, o2 = 23040, o3 = 59904,
               o4 = 133632, o5 = 281088, o6 = 576000;

    norm_input_pad_kernel<<<(BATCH * 3 * 65536 + 255) / 256, 256>>>(img, pad0);

    conv_mma_f16<1, 256><<<dim3(256, 1, BATCH), 256, CS_R1>>>(pad0, wH + o0, bs[0], pad1, 1, 64);
    conv_mma_f16<1, 256><<<dim3(256, 1, BATCH), 256, CS_R1>>>(pad1, wH + o1, bs[1], pad2, 4, 64);
    {
        long total = (long)BATCH * 32 * 128 * 128;
        maxpool_pad_kernel<<<(unsigned)((total + 255) / 256), 256>>>(pad2, pad3, 32, 256, 256);
    }
    conv_mma_f16<2, 128><<<dim3(64, 2, BATCH), 256, CS_R2>>>(pad3, wH + o2, bs[2], pad4, 4, 128);
    conv_mma_f16<2, 128><<<dim3(64, 2, BATCH), 256, CS_R2>>>(pad4, wH + o3, bs[3], pad5, 8, 128);
    {
        long total = (long)BATCH * 64 * 64 * 64;
        maxpool_pad_kernel<<<(unsigned)((total + 255) / 256), 256>>>(pad5, pad6, 64, 128, 128);
    }
    conv_mma_f16<4, 64><<<dim3(16, 4, BATCH), 256, CS_R4>>>(pad6, wH + o4, bs[4], f1, 8, 256);
    conv_mma_f16<4, 64><<<dim3(16, 4, BATCH), 256, CS_R4>>>(f1, wH + o5, bs[5], f2, 16, 256);
    conv_mma_f16<4, 64><<<dim3(16, 4, BATCH), 256, CS_R4>>>(f2, wH + o6, bs[6], f3, 16, 256);

    feat_transnorm_kernel<<<dim3(128, BATCH), dim3(32, 8), TN_SMEM>>>(f1, f2, f3, (__half2*)featT);
}

extern "C" void kernel_launch(void* const* d_in, const int* in_sizes, int n_in,
                              void* d_out, int out_size) {
    (void)in_sizes; (void)n_in; (void)out_size;

    __half2 *pad0, *pad1, *pad2, *pad3, *pad4, *pad5, *pad6, *f1, *f2, *f3, *wH;
    __half *xT, *sT;
    float *gmax;
    cudaGetSymbolAddress((void**)&pad0, g_pad0);
    cudaGetSymbolAddress((void**)&pad1, g_pad1);
    cudaGetSymbolAddress((void**)&pad2, g_pad2);
    cudaGetSymbolAddress((void**)&pad3, g_pad3);
    cudaGetSymbolAddress((void**)&pad4, g_pad4);
    cudaGetSymbolAddress((void**)&pad5, g_pad5);
    cudaGetSymbolAddress((void**)&pad6, g_pad6);
    cudaGetSymbolAddress((void**)&f1, g_f1);
    cudaGetSymbolAddress((void**)&f2, g_f2);
    cudaGetSymbolAddress((void**)&f3, g_f3);
    cudaGetSymbolAddress((void**)&xT, g_xT);
    cudaGetSymbolAddress((void**)&sT, g_sT);
    cudaGetSymbolAddress((void**)&wH, g_wH);
    cudaGetSymbolAddress((void**)&gmax, g_maxsim);

    cudaFuncSetAttribute(conv_mma_f16<1, 256>, cudaFuncAttributeMaxDynamicSharedMemorySize, CS_R1);
    cudaFuncSetAttribute(conv_mma_f16<2, 128>, cudaFuncAttributeMaxDynamicSharedMemorySize, CS_R2);
    cudaFuncSetAttribute(conv_mma_f16<4, 64>,  cudaFuncAttributeMaxDynamicSharedMemorySize, CS_R4);
    cudaFuncSetAttribute(simmax_mma_f16, cudaFuncAttributeMaxDynamicSharedMemorySize, SIM_SMEM);
    cudaFuncSetAttribute(feat_transnorm_kernel, cudaFuncAttributeMaxDynamicSharedMemorySize, TN_SMEM);

    const float* outputs = (const float*)d_in[0];
    const float* styles  = (const float*)d_in[1];
    const float* bs[7];
    for (int i = 0; i < 7; i++) bs[i] = (const float*)d_in[3 + 2 * i];

    // fused weight transform (single launch)
    wtrans_all_kernel<<<(870912 + 255) / 256, 256>>>(
        (const float*)d_in[2], (const float*)d_in[4], (const float*)d_in[6],
        (const float*)d_in[8], (const float*)d_in[10], (const float*)d_in[12],
        (const float*)d_in[14], wH);

    run_stack(outputs, wH, bs, pad0, pad1, pad2, pad3, pad4, pad5, pad6, f1, f2, f3, xT);
    run_stack(styles,  wH, bs, pad0, pad1, pad2, pad3, pad4, pad5, pad6, f1, f2, f3, sT);

    initmax_kernel<<<(BATCH * FEATN + 255) / 256, 256>>>(gmax);
    simmax_mma_f16<<<dim3(FEATN / 128, FEATN / 128, BATCH), 256, SIM_SMEM>>>(xT, sT, gmax);
    final_loss_kernel<<<1, 256>>>(gmax, (float*)d_out);
}